// round 4
// baseline (speedup 1.0000x reference)
#include <cuda_runtime.h>
#include <math.h>

#define BB 256
#define SS 512
#define DD 32
#define HH 512
#define GG 2048   // 4*HH
#define PLEN 24
#define NB 128    // persistent blocks (<=148 SMs -> all co-resident)
#define TPB 128   // threads per block

// ---------------- scratch (__device__ globals; no allocation) ----------------
__device__ float g_enc_outs[BB * SS * HH];          // 268 MB
__device__ float g_enc_proj[BB * SS * HH];          // 268 MB
__device__ float g_h0[2][BB * HH];
__device__ float g_h1[2][BB * HH];
__device__ float g_c0[BB * HH];
__device__ float g_c1[BB * HH];
__device__ float g_W0[GG * 544];                    // [ew0 | eu0], gate-interleaved rows
__device__ float g_W1[GG * 1024];                   // [ew1 | eu1]
__device__ float g_Wd0[GG * 1025];                  // [dw0 | du0]
__device__ float g_Wd1[GG * 1024];                  // [dw1 | du1]
__device__ float g_b0[GG], g_b1[GG], g_bd0[GG], g_bd1[GG];
__device__ float g_dp[BB * HH];
__device__ float g_sc[BB * SS];
__device__ float g_wsm[BB * SS];
__device__ float g_xcat[BB * 513];
__device__ float g_decin[BB];
__device__ float g_hist[BB];

// grid-wide barrier state
__device__ unsigned int g_bar_count = 0;
__device__ volatile unsigned int g_bar_gen = 0;

__device__ __forceinline__ void grid_barrier() {
    __syncthreads();
    if (threadIdx.x == 0) {
        __threadfence();
        unsigned int gen = g_bar_gen;
        if (atomicAdd(&g_bar_count, 1u) == NB - 1u) {
            g_bar_count = 0;
            __threadfence();
            g_bar_gen = gen + 1u;
        } else {
            while (g_bar_gen == gen) { __nanosleep(32); }
        }
        __threadfence();
    }
    __syncthreads();
}

// ---------------- packed f32x2 helpers (FFMA2) ----------------
__device__ __forceinline__ unsigned long long ffma2(unsigned long long a,
                                                    unsigned long long b,
                                                    unsigned long long c) {
    unsigned long long d;
    asm("fma.rn.f32x2 %0, %1, %2, %3;" : "=l"(d) : "l"(a), "l"(b), "l"(c));
    return d;
}
__device__ __forceinline__ unsigned long long dup2(float x) {
    unsigned long long d;
    unsigned xi = __float_as_uint(x);
    asm("mov.b64 %0, {%1, %1};" : "=l"(d) : "r"(xi));
    return d;
}
__device__ __forceinline__ float2 unpack2(unsigned long long v) {
    unsigned lo, hi;
    asm("mov.b64 {%0, %1}, %2;" : "=r"(lo), "=r"(hi) : "l"(v));
    return make_float2(__uint_as_float(lo), __uint_as_float(hi));
}

__device__ __forceinline__ float fast_tanh(float x) {
    float y;
    asm("tanh.approx.f32 %0, %1;" : "=f"(y) : "f"(x));
    return y;
}
__device__ __forceinline__ float sigf(float x) {
    return __fdividef(1.f, 1.f + __expf(-x));
}
__device__ __forceinline__ float tanhg(float x) {
    return 1.f - __fdividef(2.f, __expf(2.f * x) + 1.f);
}

// ---------------- weight prep: gate-interleave + concat ----------------
__global__ void prep_w(float* __restrict__ dst, const float* __restrict__ Wa, int Ka,
                       const float* __restrict__ Wb, int Kb) {
    int Kt = Ka + Kb;
    int idx = blockIdx.x * 256 + threadIdx.x;
    if (idx >= GG * Kt) return;
    int np = idx / Kt;
    int k = idx - np * Kt;
    int q = np & 3;
    int j = np >> 2;
    int n = q * HH + j;
    float v;
    if (k < Ka) v = Wa[(size_t)n * Ka + k];
    else        v = Wb[(size_t)n * Kb + (k - Ka)];
    dst[idx] = v;
}

__global__ void prep_b(float* __restrict__ dst, const float* __restrict__ bi,
                       const float* __restrict__ bh) {
    int np = blockIdx.x * 256 + threadIdx.x;
    if (np >= GG) return;
    int q = np & 3;
    int j = np >> 2;
    int n = q * HH + j;
    dst[np] = bi[n] + bh[n];
}

__global__ void zero_init(const float* __restrict__ src) {
    int i = blockIdx.x * 256 + threadIdx.x;
    if (i < BB * HH) { g_h0[0][i] = 0.f; g_h1[0][i] = 0.f; g_c0[i] = 0.f; g_c1[i] = 0.f; }
    if (i < BB) {
        size_t base = (size_t)i * SS * DD + (size_t)(SS - 1) * DD;
        g_decin[i] = src[base + (DD - 1)];   // src[:, -1, -1]
        g_hist[i]  = src[base + (DD - 15)];  // src[:, -1, -15]
    }
}

// ---------------- shared GEMM core (128 thr, 64x64 tile, 4x8 micro, FFMA2) ----
// acc[i][jp]: i = M row (4), jp = packed col-pair (4) -> 8 N cols per thread.
#define GEMM_CORE(ACC, AS, WS)                                                 \
    {                                                                          \
        _Pragma("unroll")                                                      \
        for (int kk = 0; kk < 16; kk++) {                                      \
            float4 a = *(const float4*)&AS[kk][4 * ty];                        \
            ulonglong2 wA = *(const ulonglong2*)&WS[kk][8 * tx];               \
            ulonglong2 wB = *(const ulonglong2*)&WS[kk][8 * tx + 4];           \
            unsigned long long a0 = dup2(a.x), a1 = dup2(a.y);                 \
            unsigned long long a2 = dup2(a.z), a3 = dup2(a.w);                 \
            ACC[0][0] = ffma2(a0, wA.x, ACC[0][0]);                            \
            ACC[0][1] = ffma2(a0, wA.y, ACC[0][1]);                            \
            ACC[0][2] = ffma2(a0, wB.x, ACC[0][2]);                            \
            ACC[0][3] = ffma2(a0, wB.y, ACC[0][3]);                            \
            ACC[1][0] = ffma2(a1, wA.x, ACC[1][0]);                            \
            ACC[1][1] = ffma2(a1, wA.y, ACC[1][1]);                            \
            ACC[1][2] = ffma2(a1, wB.x, ACC[1][2]);                            \
            ACC[1][3] = ffma2(a1, wB.y, ACC[1][3]);                            \
            ACC[2][0] = ffma2(a2, wA.x, ACC[2][0]);                            \
            ACC[2][1] = ffma2(a2, wA.y, ACC[2][1]);                            \
            ACC[2][2] = ffma2(a2, wB.x, ACC[2][2]);                            \
            ACC[2][3] = ffma2(a2, wB.y, ACC[2][3]);                            \
            ACC[3][0] = ffma2(a3, wA.x, ACC[3][0]);                            \
            ACC[3][1] = ffma2(a3, wA.y, ACC[3][1]);                            \
            ACC[3][2] = ffma2(a3, wB.x, ACC[3][2]);                            \
            ACC[3][3] = ffma2(a3, wB.y, ACC[3][3]);                            \
        }                                                                      \
    }

// ---------------- tile GEMM + fused LSTM cell (device fn) ----------------
// gates[b, n'] = sum_k [A1|A2][b,k] * W[n',k] + bias[n'],  n' = 4j+q interleaved.
__device__ __forceinline__ void gemm_lstm_tile(
    int tn, int tm,
    const float* __restrict__ A1, int lda1, int K1,
    const float* __restrict__ A2, int lda2, int K2,
    const float* __restrict__ W, int ldw,
    const float* __restrict__ bias,
    float* __restrict__ c_state,
    float* __restrict__ h_out,
    float* __restrict__ h_extra, size_t extra_stride,
    float (*As)[16][68], float (*Wsh)[16][68])
{
    const int tid = threadIdx.x;
    const int tx = tid & 7;
    const int ty = tid >> 3;
    const int lk = tid & 15;
    const int lr = tid >> 4;
    const int bn = tn * 64;
    const int bm = tm * 64;
    const int Kt = K1 + K2;
    const int nkt = (Kt + 15) >> 4;

    unsigned long long acc[4][4];
#pragma unroll
    for (int i = 0; i < 4; i++)
#pragma unroll
        for (int j = 0; j < 4; j++) acc[i][j] = 0ull;

    float ra[8], rw[8];
    {
        int gk = lk;
#pragma unroll
        for (int pp = 0; pp < 8; pp++) {
            int m = bm + lr + 8 * pp;
            float v = 0.f;
            if (gk < K1)       v = A1[(size_t)m * lda1 + gk];
            else if (gk < Kt)  v = A2[(size_t)m * lda2 + (gk - K1)];
            ra[pp] = v;
            int n = bn + lr + 8 * pp;
            rw[pp] = (gk < Kt) ? W[(size_t)n * ldw + gk] : 0.f;
        }
    }
    int buf = 0;
#pragma unroll
    for (int pp = 0; pp < 8; pp++) {
        As[0][lk][lr + 8 * pp] = ra[pp];
        Wsh[0][lk][lr + 8 * pp] = rw[pp];
    }
    __syncthreads();

    for (int kt = 0; kt < nkt; kt++) {
        if (kt + 1 < nkt) {
            int gk = ((kt + 1) << 4) + lk;
#pragma unroll
            for (int pp = 0; pp < 8; pp++) {
                int m = bm + lr + 8 * pp;
                float v = 0.f;
                if (gk < K1)       v = A1[(size_t)m * lda1 + gk];
                else if (gk < Kt)  v = A2[(size_t)m * lda2 + (gk - K1)];
                ra[pp] = v;
                int n = bn + lr + 8 * pp;
                rw[pp] = (gk < Kt) ? W[(size_t)n * ldw + gk] : 0.f;
            }
        }
        GEMM_CORE(acc, As[buf], Wsh[buf]);
        if (kt + 1 < nkt) {
            buf ^= 1;
#pragma unroll
            for (int pp = 0; pp < 8; pp++) {
                As[buf][lk][lr + 8 * pp] = ra[pp];
                Wsh[buf][lk][lr + 8 * pp] = rw[pp];
            }
            __syncthreads();
        }
    }

    // Epilogue: thread owns 8 consecutive n' = two gate-quads (j0, j0+1), 4 batches.
    const int ncol = bn + 8 * tx;
    const int j0 = ncol >> 2;
#pragma unroll
    for (int i = 0; i < 4; i++) {
        int b = bm + 4 * ty + i;
        float2 p0 = unpack2(acc[i][0]);
        float2 p1 = unpack2(acc[i][1]);
        float2 p2 = unpack2(acc[i][2]);
        float2 p3 = unpack2(acc[i][3]);
        // gate quad j0
        {
            float gi = sigf(p0.x + bias[ncol + 0]);
            float gf = sigf(p0.y + bias[ncol + 1]);
            float gg = tanhg(p1.x + bias[ncol + 2]);
            float go = sigf(p1.y + bias[ncol + 3]);
            float c = gf * c_state[b * HH + j0] + gi * gg;
            c_state[b * HH + j0] = c;
            float h = go * tanhg(c);
            h_out[b * HH + j0] = h;
            if (h_extra) h_extra[(size_t)b * extra_stride + j0] = h;
        }
        // gate quad j0+1
        {
            float gi = sigf(p2.x + bias[ncol + 4]);
            float gf = sigf(p2.y + bias[ncol + 5]);
            float gg = tanhg(p3.x + bias[ncol + 6]);
            float go = sigf(p3.y + bias[ncol + 7]);
            float c = gf * c_state[b * HH + j0 + 1] + gi * gg;
            c_state[b * HH + j0 + 1] = c;
            float h = go * tanhg(c);
            h_out[b * HH + j0 + 1] = h;
            if (h_extra) h_extra[(size_t)b * extra_stride + j0 + 1] = h;
        }
    }
    __syncthreads();   // protect smem reuse by next tile call
}

// ---------------- plain tile GEMM: C[m,n] = sum_k A[m,k]*W[n,k] (+bias) ------
__device__ __forceinline__ void gemm_bias_tile(
    int tn, int tm,
    const float* __restrict__ A, int lda,
    const float* __restrict__ W, int ldw,
    const float* __restrict__ bias,
    float* __restrict__ C, int N, int K,
    float (*As)[16][68], float (*Wsh)[16][68])
{
    const int tid = threadIdx.x;
    const int tx = tid & 7;
    const int ty = tid >> 3;
    const int lk = tid & 15;
    const int lr = tid >> 4;
    const int bn = tn * 64;
    const int bm = tm * 64;
    const int nkt = (K + 15) >> 4;

    unsigned long long acc[4][4];
#pragma unroll
    for (int i = 0; i < 4; i++)
#pragma unroll
        for (int j = 0; j < 4; j++) acc[i][j] = 0ull;

    float ra[8], rw[8];
    {
        int gk = lk;
#pragma unroll
        for (int pp = 0; pp < 8; pp++) {
            int m = bm + lr + 8 * pp;
            ra[pp] = (gk < K) ? A[(size_t)m * lda + gk] : 0.f;
            int n = bn + lr + 8 * pp;
            rw[pp] = (gk < K) ? W[(size_t)n * ldw + gk] : 0.f;
        }
    }
    int buf = 0;
#pragma unroll
    for (int pp = 0; pp < 8; pp++) {
        As[0][lk][lr + 8 * pp] = ra[pp];
        Wsh[0][lk][lr + 8 * pp] = rw[pp];
    }
    __syncthreads();

    for (int kt = 0; kt < nkt; kt++) {
        if (kt + 1 < nkt) {
            int gk = ((kt + 1) << 4) + lk;
#pragma unroll
            for (int pp = 0; pp < 8; pp++) {
                int m = bm + lr + 8 * pp;
                ra[pp] = (gk < K) ? A[(size_t)m * lda + gk] : 0.f;
                int n = bn + lr + 8 * pp;
                rw[pp] = (gk < K) ? W[(size_t)n * ldw + gk] : 0.f;
            }
        }
        GEMM_CORE(acc, As[buf], Wsh[buf]);
        if (kt + 1 < nkt) {
            buf ^= 1;
#pragma unroll
            for (int pp = 0; pp < 8; pp++) {
                As[buf][lk][lr + 8 * pp] = ra[pp];
                Wsh[buf][lk][lr + 8 * pp] = rw[pp];
            }
            __syncthreads();
        }
    }

#pragma unroll
    for (int i = 0; i < 4; i++) {
        int m = bm + 4 * ty + i;
        float v[8];
        float2 p;
        p = unpack2(acc[i][0]); v[0] = p.x; v[1] = p.y;
        p = unpack2(acc[i][1]); v[2] = p.x; v[3] = p.y;
        p = unpack2(acc[i][2]); v[4] = p.x; v[5] = p.y;
        p = unpack2(acc[i][3]); v[6] = p.x; v[7] = p.y;
#pragma unroll
        for (int jj = 0; jj < 8; jj++) {
            int n = bn + 8 * tx + jj;
            float w = v[jj];
            if (bias) w += bias[n];
            C[(size_t)m * N + n] = w;
        }
    }
    __syncthreads();
}

// ---------------- persistent mega-kernel ----------------
__global__ __launch_bounds__(TPB, 1) void mega(
    const float* __restrict__ src,
    const float* __restrict__ attn_W,
    const float* __restrict__ attn_b,
    const float* __restrict__ v_W,
    const float* __restrict__ fc_W,
    const float* __restrict__ fc_b,
    float* __restrict__ out)
{
    __shared__ __align__(16) float As[2][16][68];
    __shared__ __align__(16) float Wsh[2][16][68];
    __shared__ float sm[1024];

    const int bid = blockIdx.x;
    const int tid = threadIdx.x;
    const int tn = bid & 31;   // 32 n-tiles (N=2048)
    const int tm = bid >> 5;   // 4 m-tiles  (M=256)

    // ---------------- encoder: 512 steps, ONE grid barrier per step ----------------
    for (int t = 0; t < SS; t++) {
        int p = t & 1;
        gemm_lstm_tile(tn, tm, src + t * DD, SS * DD, DD,
                       g_h0[p], HH, HH, g_W0, 544, g_b0,
                       g_c0, g_h0[p ^ 1], nullptr, 0, As, Wsh);
        grid_barrier();  // h0(t) complete; L1(t) and L0(t+1) are conflict-free after
        gemm_lstm_tile(tn, tm, g_h0[p ^ 1], HH, HH,
                       g_h1[p], HH, HH, g_W1, 1024, g_b1,
                       g_c1, g_h1[p ^ 1],
                       g_enc_outs + (size_t)t * HH, (size_t)SS * HH, As, Wsh);
    }
    grid_barrier();  // enc_outs + final states complete

    // ---------------- enc_proj = enc_outs @ W_enc^T + attn_b ----------------
    // tiles: (BB*SS/64) x (HH/64) = 2048 x 8 = 16384
    for (int tt = bid; tt < 16384; tt += NB) {
        gemm_bias_tile(tt & 7, tt >> 3, g_enc_outs, HH, attn_W, 2 * HH,
                       attn_b, g_enc_proj, HH, HH, As, Wsh);
    }
    grid_barrier();

    // ---------------- decoder: 24 steps ----------------
    for (int it = 0; it < PLEN; it++) {
        int p = it & 1;

        // A: dp = h1 @ W_dec^T   (8 x 4 = 32 tiles)
        if (bid < 32) {
            gemm_bias_tile(bid & 7, bid >> 3, g_h1[p], HH, attn_W + HH, 2 * HH,
                           nullptr, g_dp, HH, HH, As, Wsh);
        }
        grid_barrier();

        // B: scores[b,s] = sum_h v[h]*tanh(ep[b,s,h]+dp[b,h]) — 2 b per block
        {
            int warp = tid >> 5, lane = tid & 31;
#pragma unroll 1
            for (int bb = 0; bb < 2; bb++) {
                int b = bid * 2 + bb;
                for (int i = tid; i < HH; i += TPB) {
                    sm[i] = g_dp[b * HH + i];
                    sm[512 + i] = v_W[i];
                }
                __syncthreads();
                const float* ep = g_enc_proj + (size_t)b * SS * HH;
                for (int s = warp; s < SS; s += 4) {
                    const float* row = ep + (size_t)s * HH;
                    float acc = 0.f;
#pragma unroll 4
                    for (int h = lane; h < HH; h += 32)
                        acc += sm[512 + h] * fast_tanh(row[h] + sm[h]);
#pragma unroll
                    for (int off = 16; off > 0; off >>= 1)
                        acc += __shfl_down_sync(0xffffffffu, acc, off);
                    if (lane == 0) g_sc[b * SS + s] = acc;
                }
                __syncthreads();
            }
        }
        grid_barrier();

        // C: softmax over s — 2 b per block
        {
#pragma unroll 1
            for (int bb = 0; bb < 2; bb++) {
                int b = bid * 2 + bb;
                float m = -1e30f;
                for (int s = tid; s < SS; s += TPB) m = fmaxf(m, g_sc[b * SS + s]);
                sm[tid] = m; __syncthreads();
                for (int off = TPB / 2; off > 0; off >>= 1) {
                    if (tid < off) sm[tid] = fmaxf(sm[tid], sm[tid + off]);
                    __syncthreads();
                }
                m = sm[0]; __syncthreads();
                float sum = 0.f;
                for (int s = tid; s < SS; s += TPB) {
                    float e = __expf(g_sc[b * SS + s] - m);
                    g_wsm[b * SS + s] = e;
                    sum += e;
                }
                sm[tid] = sum; __syncthreads();
                for (int off = TPB / 2; off > 0; off >>= 1) {
                    if (tid < off) sm[tid] += sm[tid + off];
                    __syncthreads();
                }
                float inv = 1.f / sm[0]; __syncthreads();
                for (int s = tid; s < SS; s += TPB) g_wsm[b * SS + s] *= inv;
            }
        }
        grid_barrier();

        // D: context -> xcat[:,1:513]; xcat[:,0] = dec_in — 2 b per block
        {
#pragma unroll 1
            for (int bb = 0; bb < 2; bb++) {
                int b = bid * 2 + bb;
                for (int i = tid; i < SS; i += TPB) sm[i] = g_wsm[b * SS + i];
                __syncthreads();
                const float* base = g_enc_outs + (size_t)b * SS * HH;
                float a0 = 0.f, a1 = 0.f, a2 = 0.f, a3 = 0.f;
#pragma unroll 4
                for (int s = 0; s < SS; s++) {
                    const float* r = base + (size_t)s * HH;
                    a0 += sm[s] * r[tid];
                    a1 += sm[s] * r[tid + 128];
                    a2 += sm[s] * r[tid + 256];
                    a3 += sm[s] * r[tid + 384];
                }
                g_xcat[b * 513 + 1 + tid] = a0;
                g_xcat[b * 513 + 1 + tid + 128] = a1;
                g_xcat[b * 513 + 1 + tid + 256] = a2;
                g_xcat[b * 513 + 1 + tid + 384] = a3;
                if (tid == 0) g_xcat[b * 513] = g_decin[b];
                __syncthreads();
            }
        }
        grid_barrier();

        // E: decoder LSTM layer 0 (K = 513 + 512)
        gemm_lstm_tile(tn, tm, g_xcat, 513, 513,
                       g_h0[p], HH, HH, g_Wd0, 1025, g_bd0,
                       g_c0, g_h0[p ^ 1], nullptr, 0, As, Wsh);
        grid_barrier();

        // F: decoder LSTM layer 1 (K = 1024)
        gemm_lstm_tile(tn, tm, g_h0[p ^ 1], HH, HH,
                       g_h1[p], HH, HH, g_Wd1, 1024, g_bd1,
                       g_c1, g_h1[p ^ 1], nullptr, 0, As, Wsh);
        grid_barrier();

        // G: pred + decin update (64 blocks x 4 warps = 256 b)
        if (bid < 64) {
            int warp = tid >> 5, lane = tid & 31;
            int b = bid * 4 + warp;
            const float* h1r = g_h1[p ^ 1] + b * HH;
            float acc = 0.f;
            for (int h = lane; h < HH; h += 32) acc += h1r[h] * fc_W[h];
#pragma unroll
            for (int off = 16; off > 0; off >>= 1)
                acc += __shfl_down_sync(0xffffffffu, acc, off);
            if (lane == 0) {
                float pred = acc + fc_b[0];
                out[b * PLEN + it] = pred;
                g_decin[b] = 0.8f * pred + 0.2f * g_hist[b];
            }
        }
        // no barrier needed here: the barrier after next step's stage A orders
        // G(t)'s decin write before D(t+1)'s read; dp overwrite in A(t+1) is
        // ordered after B(t) by the C/D/E/F barriers of step t.
    }
}

// ---------------- launch ----------------
extern "C" void kernel_launch(void* const* d_in, const int* in_sizes, int n_in,
                              void* d_out, int out_size) {
    (void)in_sizes; (void)n_in; (void)out_size;
    const float* src    = (const float*)d_in[0];
    const float* ew0    = (const float*)d_in[1];
    const float* eu0    = (const float*)d_in[2];
    const float* ebi0   = (const float*)d_in[3];
    const float* ebh0   = (const float*)d_in[4];
    const float* ew1    = (const float*)d_in[5];
    const float* eu1    = (const float*)d_in[6];
    const float* ebi1   = (const float*)d_in[7];
    const float* ebh1   = (const float*)d_in[8];
    const float* dw0    = (const float*)d_in[9];
    const float* du0    = (const float*)d_in[10];
    const float* dbi0   = (const float*)d_in[11];
    const float* dbh0   = (const float*)d_in[12];
    const float* dw1    = (const float*)d_in[13];
    const float* du1    = (const float*)d_in[14];
    const float* dbi1   = (const float*)d_in[15];
    const float* dbh1   = (const float*)d_in[16];
    const float* attn_W = (const float*)d_in[17];
    const float* attn_b = (const float*)d_in[18];
    const float* v_W    = (const float*)d_in[19];
    const float* fc_W   = (const float*)d_in[20];
    const float* fc_b   = (const float*)d_in[21];
    float* out = (float*)d_out;

    float *W0, *W1, *Wd0, *Wd1, *b0, *b1, *bd0, *bd1;
    cudaGetSymbolAddress((void**)&W0, g_W0);
    cudaGetSymbolAddress((void**)&W1, g_W1);
    cudaGetSymbolAddress((void**)&Wd0, g_Wd0);
    cudaGetSymbolAddress((void**)&Wd1, g_Wd1);
    cudaGetSymbolAddress((void**)&b0, g_b0);
    cudaGetSymbolAddress((void**)&b1, g_b1);
    cudaGetSymbolAddress((void**)&bd0, g_bd0);
    cudaGetSymbolAddress((void**)&bd1, g_bd1);

    // weight prep (recomputed each launch; deterministic)
    prep_w<<<(GG * 544 + 255) / 256, 256>>>(W0, ew0, DD, eu0, HH);
    prep_w<<<(GG * 1024 + 255) / 256, 256>>>(W1, ew1, HH, eu1, HH);
    prep_w<<<(GG * 1025 + 255) / 256, 256>>>(Wd0, dw0, HH + 1, du0, HH);
    prep_w<<<(GG * 1024 + 255) / 256, 256>>>(Wd1, dw1, HH, du1, HH);
    prep_b<<<(GG + 255) / 256, 256>>>(b0, ebi0, ebh0);
    prep_b<<<(GG + 255) / 256, 256>>>(b1, ebi1, ebh1);
    prep_b<<<(GG + 255) / 256, 256>>>(bd0, dbi0, dbh0);
    prep_b<<<(GG + 255) / 256, 256>>>(bd1, dbi1, dbh1);
    zero_init<<<(BB * HH + 255) / 256, 256>>>(src);

    mega<<<NB, TPB>>>(src, attn_W, attn_b, v_W, fc_W, fc_b, out);
}

// round 5
// speedup vs baseline: 1.6629x; 1.6629x over previous
#include <cuda_runtime.h>
#include <mma.h>
#include <math.h>

using namespace nvcuda;

#define BB 256
#define SS 512
#define DD 32
#define HH 512
#define GG 2048   // 4*HH
#define PLEN 24
#define NB 128    // persistent blocks (<=148 SMs -> all co-resident)
#define TPB 256   // threads per block (8 warps)

// ---------------- scratch (__device__ globals; no allocation) ----------------
__device__ float g_enc_outs[BB * SS * HH];          // 268 MB
__device__ float g_enc_proj[BB * SS * HH];          // 268 MB
__device__ float g_h0[2][BB * HH];
__device__ float g_h1[2][BB * HH];
__device__ float g_c0[BB * HH];
__device__ float g_c1[BB * HH];
__device__ float g_W0[GG * 544];                    // [ew0 | eu0], gate-interleaved rows
__device__ float g_W1[GG * 1024];                   // [ew1 | eu1]
__device__ float g_Wd0[GG * 1025];                  // [dw0 | du0]
__device__ float g_Wd1[GG * 1024];                  // [dw1 | du1]
__device__ float g_b0[GG], g_b1[GG], g_bd0[GG], g_bd1[GG];
__device__ float g_dp[BB * HH];
__device__ float g_sc[BB * SS];
__device__ float g_wsm[BB * SS];
__device__ float g_xcat[BB * 513];
__device__ float g_decin[BB];
__device__ float g_hist[BB];

// grid-wide barrier state
__device__ unsigned int g_bar_count = 0;
__device__ volatile unsigned int g_bar_gen = 0;

__device__ __forceinline__ void grid_barrier() {
    __syncthreads();
    if (threadIdx.x == 0) {
        __threadfence();
        unsigned int gen = g_bar_gen;
        if (atomicAdd(&g_bar_count, 1u) == NB - 1u) {
            g_bar_count = 0;
            __threadfence();
            g_bar_gen = gen + 1u;
        } else {
            while (g_bar_gen == gen) { __nanosleep(32); }
        }
        __threadfence();
    }
    __syncthreads();
}

__device__ __forceinline__ float fast_tanh(float x) {
    float y;
    asm("tanh.approx.f32 %0, %1;" : "=f"(y) : "f"(x));
    return y;
}
__device__ __forceinline__ float sigf(float x) {
    return __fdividef(1.f, 1.f + __expf(-x));
}
__device__ __forceinline__ float tanhg(float x) {
    return 1.f - __fdividef(2.f, __expf(2.f * x) + 1.f);
}

// ---------------- weight prep: gate-interleave + concat ----------------
__global__ void prep_w(float* __restrict__ dst, const float* __restrict__ Wa, int Ka,
                       const float* __restrict__ Wb, int Kb) {
    int Kt = Ka + Kb;
    int idx = blockIdx.x * 256 + threadIdx.x;
    if (idx >= GG * Kt) return;
    int np = idx / Kt;
    int k = idx - np * Kt;
    int q = np & 3;
    int j = np >> 2;
    int n = q * HH + j;
    float v;
    if (k < Ka) v = Wa[(size_t)n * Ka + k];
    else        v = Wb[(size_t)n * Kb + (k - Ka)];
    dst[idx] = v;
}

__global__ void prep_b(float* __restrict__ dst, const float* __restrict__ bi,
                       const float* __restrict__ bh) {
    int np = blockIdx.x * 256 + threadIdx.x;
    if (np >= GG) return;
    int q = np & 3;
    int j = np >> 2;
    int n = q * HH + j;
    dst[np] = bi[n] + bh[n];
}

__global__ void zero_init(const float* __restrict__ src) {
    int i = blockIdx.x * 256 + threadIdx.x;
    if (i < BB * HH) { g_h0[0][i] = 0.f; g_h1[0][i] = 0.f; g_c0[i] = 0.f; g_c1[i] = 0.f; }
    if (i < BB) {
        size_t base = (size_t)i * SS * DD + (size_t)(SS - 1) * DD;
        g_decin[i] = src[base + (DD - 1)];   // src[:, -1, -1]
        g_hist[i]  = src[base + (DD - 15)];  // src[:, -1, -15]
    }
}

// ---------------- wmma tf32 GEMM core -----------------------------------------
// Tile 64(m) x 64(n), K chunks of 32. 8 warps: 4(m) x 2(n); each warp computes
// 16(m) x 32(n) = two 16x16 acc frags. Result lands in Cs[64][68] (smem).
typedef wmma::fragment<wmma::matrix_a, 16, 16, 8, wmma::precision::tf32, wmma::row_major> AFrag;
typedef wmma::fragment<wmma::matrix_b, 16, 16, 8, wmma::precision::tf32, wmma::col_major> BFrag;
typedef wmma::fragment<wmma::accumulator, 16, 16, 8, float> CFrag;

// Compute gates tile into Cs. A = [A1 | A2] (concat along K), C = A * W^T.
__device__ __forceinline__ void gemm_core_tf32(
    int bn, int bm,
    const float* __restrict__ A1, int lda1, int K1,
    const float* __restrict__ A2, int lda2, int K2,
    const float* __restrict__ W, int ldw,
    float (*As)[36], float (*Ws)[36], float (*Cs)[68])
{
    const int tid = threadIdx.x;
    const int warp = tid >> 5;
    const int wm = warp & 3;        // 0..3 -> 16-row group
    const int wn = warp >> 2;       // 0..1 -> 32-col group
    const int Kt = K1 + K2;
    const int nck = (Kt + 31) >> 5;

    CFrag acc[2];
    wmma::fill_fragment(acc[0], 0.f);
    wmma::fill_fragment(acc[1], 0.f);

    float ra[8], rw[8];
    // prefetch chunk 0
#pragma unroll
    for (int t = 0; t < 8; t++) {
        int i = tid + t * TPB;            // 0..2047
        int row = i >> 5, kk = i & 31;
        int gk = kk;
        float va = 0.f;
        int m = bm + row;
        if (gk < K1)      va = A1[(size_t)m * lda1 + gk];
        else if (gk < Kt) va = A2[(size_t)m * lda2 + (gk - K1)];
        ra[t] = va;
        int n = bn + row;
        rw[t] = (gk < Kt) ? W[(size_t)n * ldw + gk] : 0.f;
    }

    for (int ck = 0; ck < nck; ck++) {
#pragma unroll
        for (int t = 0; t < 8; t++) {
            int i = tid + t * TPB;
            int row = i >> 5, kk = i & 31;
            As[row][kk] = ra[t];
            Ws[row][kk] = rw[t];
        }
        __syncthreads();
        if (ck + 1 < nck) {
            int k0 = (ck + 1) << 5;
#pragma unroll
            for (int t = 0; t < 8; t++) {
                int i = tid + t * TPB;
                int row = i >> 5, kk = i & 31;
                int gk = k0 + kk;
                float va = 0.f;
                int m = bm + row;
                if (gk < K1)      va = A1[(size_t)m * lda1 + gk];
                else if (gk < Kt) va = A2[(size_t)m * lda2 + (gk - K1)];
                ra[t] = va;
                int n = bn + row;
                rw[t] = (gk < Kt) ? W[(size_t)n * ldw + gk] : 0.f;
            }
        }
#pragma unroll
        for (int k8 = 0; k8 < 4; k8++) {
            AFrag af;
            wmma::load_matrix_sync(af, &As[wm * 16][k8 * 8], 36);
#pragma unroll
            for (int e = 0; e < af.num_elements; e++)
                af.x[e] = wmma::__float_to_tf32(af.x[e]);
#pragma unroll
            for (int j = 0; j < 2; j++) {
                BFrag bf;
                wmma::load_matrix_sync(bf, &Ws[wn * 32 + j * 16][k8 * 8], 36);
#pragma unroll
                for (int e = 0; e < bf.num_elements; e++)
                    bf.x[e] = wmma::__float_to_tf32(bf.x[e]);
                wmma::mma_sync(acc[j], af, bf, acc[j]);
            }
        }
        __syncthreads();
    }

    wmma::store_matrix_sync(&Cs[wm * 16][wn * 32], acc[0], 68, wmma::mem_row_major);
    wmma::store_matrix_sync(&Cs[wm * 16][wn * 32 + 16], acc[1], 68, wmma::mem_row_major);
    __syncthreads();
}

// ---------------- tile GEMM + fused LSTM cell ----------------
// gates[b, n'] with n' = 4j+q gate-interleaved; epilogue off smem Cs.
__device__ __forceinline__ void gemm_lstm_tile(
    int tn, int tm,
    const float* __restrict__ A1, int lda1, int K1,
    const float* __restrict__ A2, int lda2, int K2,
    const float* __restrict__ W, int ldw,
    const float* __restrict__ bias,
    float* __restrict__ c_state,
    float* __restrict__ h_out,
    float* __restrict__ h_extra, size_t extra_stride,
    float (*As)[36], float (*Ws)[36], float (*Cs)[68])
{
    const int bn = tn * 64;
    const int bm = tm * 64;
    gemm_core_tf32(bn, bm, A1, lda1, K1, A2, lda2, K2, W, ldw, As, Ws, Cs);

    const int tid = threadIdx.x;
    // 64 rows x 16 gate-quads = 1024 work items
#pragma unroll
    for (int t = 0; t < 4; t++) {
        int idx = tid + t * TPB;
        int r = idx >> 4;          // row in tile (batch)
        int jj = idx & 15;         // gate-quad within tile
        int b = bm + r;
        int ncol = bn + 4 * jj;
        int j = ncol >> 2;
        float gi = sigf(Cs[r][4 * jj + 0] + bias[ncol + 0]);
        float gf = sigf(Cs[r][4 * jj + 1] + bias[ncol + 1]);
        float gg = tanhg(Cs[r][4 * jj + 2] + bias[ncol + 2]);
        float go = sigf(Cs[r][4 * jj + 3] + bias[ncol + 3]);
        float c = gf * c_state[b * HH + j] + gi * gg;
        c_state[b * HH + j] = c;
        float h = go * tanhg(c);
        h_out[b * HH + j] = h;
        if (h_extra) h_extra[(size_t)b * extra_stride + j] = h;
    }
    __syncthreads();
}

// ---------------- plain tile GEMM: C[m,n] = sum_k A[m,k]*W[n,k] (+bias) ------
__device__ __forceinline__ void gemm_bias_tile(
    int tn, int tm,
    const float* __restrict__ A, int lda,
    const float* __restrict__ W, int ldw,
    const float* __restrict__ bias,
    float* __restrict__ C, int N, int K,
    float (*As)[36], float (*Ws)[36], float (*Cs)[68])
{
    const int bn = tn * 64;
    const int bm = tm * 64;
    gemm_core_tf32(bn, bm, A, lda, K, (const float*)0, 0, 0, W, ldw, As, Ws, Cs);

    const int tid = threadIdx.x;
    // 64 rows x 16 float4 = 1024 stores
#pragma unroll
    for (int t = 0; t < 4; t++) {
        int idx = tid + t * TPB;
        int r = idx >> 4;
        int c4 = idx & 15;
        int m = bm + r;
        int n = bn + 4 * c4;
        float4 v = *(const float4*)&Cs[r][4 * c4];
        if (bias) {
            float4 bv = *(const float4*)&bias[n];
            v.x += bv.x; v.y += bv.y; v.z += bv.z; v.w += bv.w;
        }
        *(float4*)&C[(size_t)m * N + n] = v;
    }
    __syncthreads();
}

// ---------------- persistent mega-kernel ----------------
__global__ __launch_bounds__(TPB, 1) void mega(
    const float* __restrict__ src,
    const float* __restrict__ attn_W,
    const float* __restrict__ attn_b,
    const float* __restrict__ v_W,
    const float* __restrict__ fc_W,
    const float* __restrict__ fc_b,
    float* __restrict__ out)
{
    __shared__ __align__(16) float As[64][36];
    __shared__ __align__(16) float Ws[64][36];
    __shared__ __align__(16) float Cs[64][68];
    __shared__ float sm[1024];

    const int bid = blockIdx.x;
    const int tid = threadIdx.x;
    const int tn = bid & 31;   // 32 n-tiles (N=2048)
    const int tm = bid >> 5;   // 4 m-tiles  (M=256)

    // ---------------- encoder: 512 steps, ONE grid barrier per step ----------------
    for (int t = 0; t < SS; t++) {
        int p = t & 1;
        gemm_lstm_tile(tn, tm, src + t * DD, SS * DD, DD,
                       g_h0[p], HH, HH, g_W0, 544, g_b0,
                       g_c0, g_h0[p ^ 1], nullptr, 0, As, Ws, Cs);
        grid_barrier();  // h0(t) complete; L1(t) and L0(t+1) are conflict-free after
        gemm_lstm_tile(tn, tm, g_h0[p ^ 1], HH, HH,
                       g_h1[p], HH, HH, g_W1, 1024, g_b1,
                       g_c1, g_h1[p ^ 1],
                       g_enc_outs + (size_t)t * HH, (size_t)SS * HH, As, Ws, Cs);
    }
    grid_barrier();  // enc_outs + final states complete

    // ---------------- enc_proj = enc_outs @ W_enc^T + attn_b ----------------
    // tiles: (BB*SS/64) x (HH/64) = 2048 x 8 = 16384
    for (int tt = bid; tt < 16384; tt += NB) {
        gemm_bias_tile(tt & 7, tt >> 3, g_enc_outs, HH, attn_W, 2 * HH,
                       attn_b, g_enc_proj, HH, HH, As, Ws, Cs);
    }
    grid_barrier();

    // ---------------- decoder: 24 steps ----------------
    for (int it = 0; it < PLEN; it++) {
        int p = it & 1;

        // A: dp = h1 @ W_dec^T   (8 x 4 = 32 tiles)
        if (bid < 32) {
            gemm_bias_tile(bid & 7, bid >> 3, g_h1[p], HH, attn_W + HH, 2 * HH,
                           nullptr, g_dp, HH, HH, As, Ws, Cs);
        }
        grid_barrier();

        // B: scores[b,s] = sum_h v[h]*tanh(ep[b,s,h]+dp[b,h]) — 2 b per block
        {
            int warp = tid >> 5, lane = tid & 31;
#pragma unroll 1
            for (int bb = 0; bb < 2; bb++) {
                int b = bid * 2 + bb;
                for (int i = tid; i < HH; i += TPB) {
                    sm[i] = g_dp[b * HH + i];
                    sm[512 + i] = v_W[i];
                }
                __syncthreads();
                const float* ep = g_enc_proj + (size_t)b * SS * HH;
                for (int s = warp; s < SS; s += 8) {
                    const float* row = ep + (size_t)s * HH;
                    float acc = 0.f;
#pragma unroll 4
                    for (int h = lane; h < HH; h += 32)
                        acc += sm[512 + h] * fast_tanh(row[h] + sm[h]);
#pragma unroll
                    for (int off = 16; off > 0; off >>= 1)
                        acc += __shfl_down_sync(0xffffffffu, acc, off);
                    if (lane == 0) g_sc[b * SS + s] = acc;
                }
                __syncthreads();
            }
        }
        grid_barrier();

        // C: softmax over s — 2 b per block
        {
#pragma unroll 1
            for (int bb = 0; bb < 2; bb++) {
                int b = bid * 2 + bb;
                float m = -1e30f;
                for (int s = tid; s < SS; s += TPB) m = fmaxf(m, g_sc[b * SS + s]);
                sm[tid] = m; __syncthreads();
                for (int off = TPB / 2; off > 0; off >>= 1) {
                    if (tid < off) sm[tid] = fmaxf(sm[tid], sm[tid + off]);
                    __syncthreads();
                }
                m = sm[0]; __syncthreads();
                float sum = 0.f;
                for (int s = tid; s < SS; s += TPB) {
                    float e = __expf(g_sc[b * SS + s] - m);
                    g_wsm[b * SS + s] = e;
                    sum += e;
                }
                sm[tid] = sum; __syncthreads();
                for (int off = TPB / 2; off > 0; off >>= 1) {
                    if (tid < off) sm[tid] += sm[tid + off];
                    __syncthreads();
                }
                float inv = 1.f / sm[0]; __syncthreads();
                for (int s = tid; s < SS; s += TPB) g_wsm[b * SS + s] *= inv;
            }
        }
        grid_barrier();

        // D: context -> xcat[:,1:513]; xcat[:,0] = dec_in — 2 b per block
        {
#pragma unroll 1
            for (int bb = 0; bb < 2; bb++) {
                int b = bid * 2 + bb;
                for (int i = tid; i < SS; i += TPB) sm[i] = g_wsm[b * SS + i];
                __syncthreads();
                const float* base = g_enc_outs + (size_t)b * SS * HH;
                float a0 = 0.f, a1 = 0.f;
#pragma unroll 4
                for (int s = 0; s < SS; s++) {
                    const float* r = base + (size_t)s * HH;
                    a0 += sm[s] * r[tid];
                    a1 += sm[s] * r[tid + 256];
                }
                g_xcat[b * 513 + 1 + tid] = a0;
                g_xcat[b * 513 + 1 + tid + 256] = a1;
                if (tid == 0) g_xcat[b * 513] = g_decin[b];
                __syncthreads();
            }
        }
        grid_barrier();

        // E: decoder LSTM layer 0 (K = 513 + 512)
        gemm_lstm_tile(tn, tm, g_xcat, 513, 513,
                       g_h0[p], HH, HH, g_Wd0, 1025, g_bd0,
                       g_c0, g_h0[p ^ 1], nullptr, 0, As, Ws, Cs);
        grid_barrier();

        // F: decoder LSTM layer 1 (K = 1024)
        gemm_lstm_tile(tn, tm, g_h0[p ^ 1], HH, HH,
                       g_h1[p], HH, HH, g_Wd1, 1024, g_bd1,
                       g_c1, g_h1[p ^ 1], nullptr, 0, As, Ws, Cs);
        grid_barrier();

        // G: pred + decin update (32 blocks x 8 warps = 256 b)
        if (bid < 32) {
            int warp = tid >> 5, lane = tid & 31;
            int b = bid * 8 + warp;
            const float* h1r = g_h1[p ^ 1] + b * HH;
            float acc = 0.f;
            for (int h = lane; h < HH; h += 32) acc += h1r[h] * fc_W[h];
#pragma unroll
            for (int off = 16; off > 0; off >>= 1)
                acc += __shfl_down_sync(0xffffffffu, acc, off);
            if (lane == 0) {
                float pred = acc + fc_b[0];
                out[b * PLEN + it] = pred;
                g_decin[b] = 0.8f * pred + 0.2f * g_hist[b];
            }
        }
        // no barrier needed here: the barrier after next step's stage A orders
        // G(t)'s decin write before D(t+1)'s read; dp overwrite in A(t+1) is
        // ordered after B(t) by the C/D/E/F barriers of step t.
    }
}

// ---------------- launch ----------------
extern "C" void kernel_launch(void* const* d_in, const int* in_sizes, int n_in,
                              void* d_out, int out_size) {
    (void)in_sizes; (void)n_in; (void)out_size;
    const float* src    = (const float*)d_in[0];
    const float* ew0    = (const float*)d_in[1];
    const float* eu0    = (const float*)d_in[2];
    const float* ebi0   = (const float*)d_in[3];
    const float* ebh0   = (const float*)d_in[4];
    const float* ew1    = (const float*)d_in[5];
    const float* eu1    = (const float*)d_in[6];
    const float* ebi1   = (const float*)d_in[7];
    const float* ebh1   = (const float*)d_in[8];
    const float* dw0    = (const float*)d_in[9];
    const float* du0    = (const float*)d_in[10];
    const float* dbi0   = (const float*)d_in[11];
    const float* dbh0   = (const float*)d_in[12];
    const float* dw1    = (const float*)d_in[13];
    const float* du1    = (const float*)d_in[14];
    const float* dbi1   = (const float*)d_in[15];
    const float* dbh1   = (const float*)d_in[16];
    const float* attn_W = (const float*)d_in[17];
    const float* attn_b = (const float*)d_in[18];
    const float* v_W    = (const float*)d_in[19];
    const float* fc_W   = (const float*)d_in[20];
    const float* fc_b   = (const float*)d_in[21];
    float* out = (float*)d_out;

    float *W0, *W1, *Wd0, *Wd1, *b0, *b1, *bd0, *bd1;
    cudaGetSymbolAddress((void**)&W0, g_W0);
    cudaGetSymbolAddress((void**)&W1, g_W1);
    cudaGetSymbolAddress((void**)&Wd0, g_Wd0);
    cudaGetSymbolAddress((void**)&Wd1, g_Wd1);
    cudaGetSymbolAddress((void**)&b0, g_b0);
    cudaGetSymbolAddress((void**)&b1, g_b1);
    cudaGetSymbolAddress((void**)&bd0, g_bd0);
    cudaGetSymbolAddress((void**)&bd1, g_bd1);

    // weight prep (recomputed each launch; deterministic)
    prep_w<<<(GG * 544 + 255) / 256, 256>>>(W0, ew0, DD, eu0, HH);
    prep_w<<<(GG * 1024 + 255) / 256, 256>>>(W1, ew1, HH, eu1, HH);
    prep_w<<<(GG * 1025 + 255) / 256, 256>>>(Wd0, dw0, HH + 1, du0, HH);
    prep_w<<<(GG * 1024 + 255) / 256, 256>>>(Wd1, dw1, HH, du1, HH);
    prep_b<<<(GG + 255) / 256, 256>>>(b0, ebi0, ebh0);
    prep_b<<<(GG + 255) / 256, 256>>>(b1, ebi1, ebh1);
    prep_b<<<(GG + 255) / 256, 256>>>(bd0, dbi0, dbh0);
    prep_b<<<(GG + 255) / 256, 256>>>(bd1, dbi1, dbh1);
    zero_init<<<(BB * HH + 255) / 256, 256>>>(src);

    mega<<<NB, TPB>>>(src, attn_W, attn_b, v_W, fc_W, fc_b, out);
}

// round 6
// speedup vs baseline: 1.7602x; 1.0585x over previous
#include <cuda_runtime.h>
#include <mma.h>
#include <math.h>

using namespace nvcuda;

#define BB 256
#define SS 512
#define DD 32
#define HH 512
#define GG 2048   // 4*HH
#define PLEN 24
#define NB 128    // persistent blocks (<=148 SMs -> all co-resident)
#define TPB 256   // threads per block (8 warps)

// ---------------- scratch (__device__ globals; no allocation) ----------------
__device__ float g_enc_outs[BB * SS * HH];          // 268 MB
__device__ float g_enc_proj[BB * SS * HH];          // 268 MB
__device__ float g_h0[2][BB * HH];
__device__ float g_h1[2][BB * HH];
__device__ float g_c0[BB * HH];
__device__ float g_c1[BB * HH];
__device__ float g_W0[GG * 544];                    // [ew0 | eu0], gate-interleaved rows
__device__ float g_W1[GG * 1024];                   // [ew1 | eu1]
__device__ float g_Wd0[GG * 1025];                  // [dw0 | du0]
__device__ float g_Wd1[GG * 1024];                  // [dw1 | du1]
__device__ float g_b0[GG], g_b1[GG], g_bd0[GG], g_bd1[GG];
__device__ float g_dp[BB * HH];
__device__ float g_sc[BB * SS];
__device__ float g_wsm[BB * SS];
__device__ float g_xcat[BB * 513];
__device__ float g_decin[BB];
__device__ float g_hist[BB];

// grid-wide barrier state
__device__ unsigned int g_bar_count = 0;
__device__ volatile unsigned int g_bar_gen = 0;

__device__ __forceinline__ void grid_barrier() {
    __syncthreads();
    if (threadIdx.x == 0) {
        __threadfence();
        unsigned int gen = g_bar_gen;
        if (atomicAdd(&g_bar_count, 1u) == NB - 1u) {
            g_bar_count = 0;
            __threadfence();
            g_bar_gen = gen + 1u;
        } else {
            while (g_bar_gen == gen) { __nanosleep(32); }
        }
        __threadfence();
    }
    __syncthreads();
}

__device__ __forceinline__ float fast_tanh(float x) {
    float y;
    asm("tanh.approx.f32 %0, %1;" : "=f"(y) : "f"(x));
    return y;
}
__device__ __forceinline__ float sigf(float x) {
    return __fdividef(1.f, 1.f + __expf(-x));
}
__device__ __forceinline__ float tanhg(float x) {
    return 1.f - __fdividef(2.f, __expf(2.f * x) + 1.f);
}
__device__ __forceinline__ float to_tf32(float x) {
    float y;
    asm("cvt.rna.tf32.f32 %0, %1;" : "=f"(y) : "f"(x));
    return y;
}

// ---------------- fused prep: interleave weights, biases, init state ---------
// n' = 4j+q maps to original row n = q*HH + j.
__device__ __forceinline__ void interleave_region(
    float* __restrict__ dst, const float* __restrict__ Wa, int Ka,
    const float* __restrict__ Wb, int Kb, int base, int stride) {
    int Kt = Ka + Kb;
    int total = GG * Kt;
    for (int idx = base; idx < total; idx += stride) {
        int np = idx / Kt;
        int k = idx - np * Kt;
        int q = np & 3;
        int j = np >> 2;
        int n = q * HH + j;
        float v;
        if (k < Ka) v = Wa[(size_t)n * Ka + k];
        else        v = Wb[(size_t)n * Kb + (k - Ka)];
        dst[idx] = v;
    }
}

__global__ void prep_all(
    const float* __restrict__ src,
    const float* __restrict__ ew0, const float* __restrict__ eu0,
    const float* __restrict__ ebi0, const float* __restrict__ ebh0,
    const float* __restrict__ ew1, const float* __restrict__ eu1,
    const float* __restrict__ ebi1, const float* __restrict__ ebh1,
    const float* __restrict__ dw0, const float* __restrict__ du0,
    const float* __restrict__ dbi0, const float* __restrict__ dbh0,
    const float* __restrict__ dw1, const float* __restrict__ du1,
    const float* __restrict__ dbi1, const float* __restrict__ dbh1)
{
    int base = blockIdx.x * blockDim.x + threadIdx.x;
    int stride = gridDim.x * blockDim.x;

    interleave_region(g_W0, ew0, DD, eu0, HH, base, stride);
    interleave_region(g_W1, ew1, HH, eu1, HH, base, stride);
    interleave_region(g_Wd0, dw0, HH + 1, du0, HH, base, stride);
    interleave_region(g_Wd1, dw1, HH, du1, HH, base, stride);

    for (int np = base; np < GG; np += stride) {
        int q = np & 3;
        int j = np >> 2;
        int n = q * HH + j;
        g_b0[np] = ebi0[n] + ebh0[n];
        g_b1[np] = ebi1[n] + ebh1[n];
        g_bd0[np] = dbi0[n] + dbh0[n];
        g_bd1[np] = dbi1[n] + dbh1[n];
    }
    for (int i = base; i < BB * HH; i += stride) {
        g_h0[0][i] = 0.f; g_h1[0][i] = 0.f; g_c0[i] = 0.f; g_c1[i] = 0.f;
    }
    for (int i = base; i < BB; i += stride) {
        size_t o = (size_t)i * SS * DD + (size_t)(SS - 1) * DD;
        g_decin[i] = src[o + (DD - 1)];   // src[:, -1, -1]
        g_hist[i]  = src[o + (DD - 15)];  // src[:, -1, -15]
    }
}

// ---------------- wmma tf32 GEMM core -----------------------------------------
// Tile 64(m) x 64(n), K chunks of 32, double-buffered smem, ONE sync per chunk.
// 8 warps: 4(m) x 2(n); each warp -> two 16x16 acc frags.
// smem_raw layout (floats): A buf0 [0,2304) | A buf1 [2304,4608)
//                           W buf0 [4608,6912) | W buf1 [6912,9216)
// C tile (64x68) aliases [0,4352) after compute (guarded by syncs).
typedef wmma::fragment<wmma::matrix_a, 16, 16, 8, wmma::precision::tf32, wmma::row_major> AFrag;
typedef wmma::fragment<wmma::matrix_b, 16, 16, 8, wmma::precision::tf32, wmma::col_major> BFrag;
typedef wmma::fragment<wmma::accumulator, 16, 16, 8, float> CFrag;

__device__ __forceinline__ void gemm_core_tf32(
    int bn, int bm,
    const float* __restrict__ A1, int lda1, int K1,
    const float* __restrict__ A2, int lda2, int K2,
    const float* __restrict__ W, int ldw,
    float* __restrict__ smem_raw)
{
    const int tid = threadIdx.x;
    const int warp = tid >> 5;
    const int wm = warp & 3;        // 0..3 -> 16-row group
    const int wn = warp >> 2;       // 0..1 -> 32-col group
    const int Kt = K1 + K2;
    const int nck = (Kt + 31) >> 5;
    const int row = tid >> 5;       // base row for loads (8 rows apart per t)
    const int kk = tid & 31;

    CFrag acc[2];
    wmma::fill_fragment(acc[0], 0.f);
    wmma::fill_fragment(acc[1], 0.f);

    float ra[8], rw[8];

#define PREF(K0)                                                               \
    {                                                                          \
        int gk = (K0) + kk;                                                    \
        _Pragma("unroll")                                                      \
        for (int t = 0; t < 8; t++) {                                          \
            int r = row + t * 8;                                               \
            float va = 0.f;                                                    \
            int m = bm + r;                                                    \
            if (gk < K1)      va = A1[(size_t)m * lda1 + gk];                  \
            else if (gk < Kt) va = A2[(size_t)m * lda2 + (gk - K1)];           \
            ra[t] = to_tf32(va);                                               \
            int n = bn + r;                                                    \
            rw[t] = (gk < Kt) ? to_tf32(W[(size_t)n * ldw + gk]) : 0.f;        \
        }                                                                      \
    }

#define STORE(BUF)                                                             \
    {                                                                          \
        float* Ab = smem_raw + (BUF) * 2304;                                   \
        float* Wb = smem_raw + 4608 + (BUF) * 2304;                            \
        _Pragma("unroll")                                                      \
        for (int t = 0; t < 8; t++) {                                          \
            int r = row + t * 8;                                               \
            Ab[r * 36 + kk] = ra[t];                                           \
            Wb[r * 36 + kk] = rw[t];                                           \
        }                                                                      \
    }

    PREF(0);
    STORE(0);
    __syncthreads();
    int buf = 0;

    for (int ck = 0; ck < nck; ck++) {
        if (ck + 1 < nck) PREF((ck + 1) << 5);
        const float* Ab = smem_raw + buf * 2304;
        const float* Wb = smem_raw + 4608 + buf * 2304;
#pragma unroll
        for (int k8 = 0; k8 < 4; k8++) {
            AFrag af;
            wmma::load_matrix_sync(af, &Ab[(wm * 16) * 36 + k8 * 8], 36);
            BFrag bf0, bf1;
            wmma::load_matrix_sync(bf0, &Wb[(wn * 32) * 36 + k8 * 8], 36);
            wmma::load_matrix_sync(bf1, &Wb[(wn * 32 + 16) * 36 + k8 * 8], 36);
            wmma::mma_sync(acc[0], af, bf0, acc[0]);
            wmma::mma_sync(acc[1], af, bf1, acc[1]);
        }
        if (ck + 1 < nck) {
            buf ^= 1;
            STORE(buf);
            __syncthreads();
        }
    }
#undef PREF
#undef STORE

    __syncthreads();   // all mma smem reads done before aliasing C onto raw
    float (*Cs)[68] = (float(*)[68])smem_raw;
    wmma::store_matrix_sync(&Cs[wm * 16][wn * 32], acc[0], 68, wmma::mem_row_major);
    wmma::store_matrix_sync(&Cs[wm * 16][wn * 32 + 16], acc[1], 68, wmma::mem_row_major);
    __syncthreads();
}

// ---------------- tile GEMM + fused LSTM cell ----------------
__device__ __forceinline__ void gemm_lstm_tile(
    int tn, int tm,
    const float* __restrict__ A1, int lda1, int K1,
    const float* __restrict__ A2, int lda2, int K2,
    const float* __restrict__ W, int ldw,
    const float* __restrict__ bias,
    float* __restrict__ c_state,
    float* __restrict__ h_out,
    float* __restrict__ h_extra, size_t extra_stride,
    float* __restrict__ smem_raw)
{
    const int bn = tn * 64;
    const int bm = tm * 64;
    gemm_core_tf32(bn, bm, A1, lda1, K1, A2, lda2, K2, W, ldw, smem_raw);
    float (*Cs)[68] = (float(*)[68])smem_raw;

    const int tid = threadIdx.x;
    // 64 rows x 16 gate-quads = 1024 work items
#pragma unroll
    for (int t = 0; t < 4; t++) {
        int idx = tid + t * TPB;
        int r = idx >> 4;          // row in tile (batch)
        int jj = idx & 15;         // gate-quad within tile
        int b = bm + r;
        int ncol = bn + 4 * jj;
        int j = ncol >> 2;
        float gi = sigf(Cs[r][4 * jj + 0] + bias[ncol + 0]);
        float gf = sigf(Cs[r][4 * jj + 1] + bias[ncol + 1]);
        float gg = tanhg(Cs[r][4 * jj + 2] + bias[ncol + 2]);
        float go = sigf(Cs[r][4 * jj + 3] + bias[ncol + 3]);
        float c = gf * c_state[b * HH + j] + gi * gg;
        c_state[b * HH + j] = c;
        float h = go * tanhg(c);
        h_out[b * HH + j] = h;
        if (h_extra) h_extra[(size_t)b * extra_stride + j] = h;
    }
    __syncthreads();
}

// ---------------- plain tile GEMM: C[m,n] = sum_k A[m,k]*W[n,k] (+bias) ------
__device__ __forceinline__ void gemm_bias_tile(
    int tn, int tm,
    const float* __restrict__ A, int lda,
    const float* __restrict__ W, int ldw,
    const float* __restrict__ bias,
    float* __restrict__ C, int N, int K,
    float* __restrict__ smem_raw)
{
    const int bn = tn * 64;
    const int bm = tm * 64;
    gemm_core_tf32(bn, bm, A, lda, K, (const float*)0, 0, 0, W, ldw, smem_raw);
    float (*Cs)[68] = (float(*)[68])smem_raw;

    const int tid = threadIdx.x;
#pragma unroll
    for (int t = 0; t < 4; t++) {
        int idx = tid + t * TPB;
        int r = idx >> 4;
        int c4 = idx & 15;
        int m = bm + r;
        int n = bn + 4 * c4;
        float4 v = *(const float4*)&Cs[r][4 * c4];
        if (bias) {
            float4 bv = *(const float4*)&bias[n];
            v.x += bv.x; v.y += bv.y; v.z += bv.z; v.w += bv.w;
        }
        *(float4*)&C[(size_t)m * N + n] = v;
    }
    __syncthreads();
}

// ---------------- persistent mega-kernel ----------------
__global__ __launch_bounds__(TPB, 1) void mega(
    const float* __restrict__ src,
    const float* __restrict__ attn_W,
    const float* __restrict__ attn_b,
    const float* __restrict__ v_W,
    const float* __restrict__ fc_W,
    const float* __restrict__ fc_b,
    float* __restrict__ out)
{
    __shared__ __align__(16) float raw[9216];   // A/W double buffers; C aliases
    __shared__ float sm[1024];

    const int bid = blockIdx.x;
    const int tid = threadIdx.x;
    const int tn = bid & 31;   // 32 n-tiles (N=2048)
    const int tm = bid >> 5;   // 4 m-tiles  (M=256)

    // ---------------- encoder: 512 steps, ONE grid barrier per step ----------------
    for (int t = 0; t < SS; t++) {
        int p = t & 1;
        gemm_lstm_tile(tn, tm, src + t * DD, SS * DD, DD,
                       g_h0[p], HH, HH, g_W0, 544, g_b0,
                       g_c0, g_h0[p ^ 1], nullptr, 0, raw);
        grid_barrier();  // h0(t) complete; L1(t) and L0(t+1) are conflict-free after
        gemm_lstm_tile(tn, tm, g_h0[p ^ 1], HH, HH,
                       g_h1[p], HH, HH, g_W1, 1024, g_b1,
                       g_c1, g_h1[p ^ 1],
                       g_enc_outs + (size_t)t * HH, (size_t)SS * HH, raw);
    }
    grid_barrier();  // enc_outs + final states complete

    // ---------------- enc_proj = enc_outs @ W_enc^T + attn_b ----------------
    // tiles: (BB*SS/64) x (HH/64) = 2048 x 8 = 16384
    for (int tt = bid; tt < 16384; tt += NB) {
        gemm_bias_tile(tt & 7, tt >> 3, g_enc_outs, HH, attn_W, 2 * HH,
                       attn_b, g_enc_proj, HH, HH, raw);
    }
    grid_barrier();

    // ---------------- decoder: 24 steps ----------------
    for (int it = 0; it < PLEN; it++) {
        int p = it & 1;

        // A: dp = h1 @ W_dec^T   (8 x 4 = 32 tiles)
        if (bid < 32) {
            gemm_bias_tile(bid & 7, bid >> 3, g_h1[p], HH, attn_W + HH, 2 * HH,
                           nullptr, g_dp, HH, HH, raw);
        }
        grid_barrier();

        // B: scores[b,s] = sum_h v[h]*tanh(ep[b,s,h]+dp[b,h]) — 2 b per block
        {
            int warp = tid >> 5, lane = tid & 31;
#pragma unroll 1
            for (int bb = 0; bb < 2; bb++) {
                int b = bid * 2 + bb;
                for (int i = tid; i < HH; i += TPB) {
                    sm[i] = g_dp[b * HH + i];
                    sm[512 + i] = v_W[i];
                }
                __syncthreads();
                const float* ep = g_enc_proj + (size_t)b * SS * HH;
                for (int s = warp; s < SS; s += 8) {
                    const float* row = ep + (size_t)s * HH;
                    float acc = 0.f;
#pragma unroll
                    for (int h0 = 0; h0 < 4; h0++) {
                        int h = h0 * 128 + lane * 4;
                        float4 r = *(const float4*)&row[h];
                        float4 d = *(const float4*)&sm[h];
                        float4 v = *(const float4*)&sm[512 + h];
                        acc += v.x * fast_tanh(r.x + d.x)
                             + v.y * fast_tanh(r.y + d.y)
                             + v.z * fast_tanh(r.z + d.z)
                             + v.w * fast_tanh(r.w + d.w);
                    }
#pragma unroll
                    for (int off = 16; off > 0; off >>= 1)
                        acc += __shfl_down_sync(0xffffffffu, acc, off);
                    if (lane == 0) g_sc[b * SS + s] = acc;
                }
                __syncthreads();
            }
        }
        grid_barrier();

        // C: softmax over s — 2 b per block
        {
#pragma unroll 1
            for (int bb = 0; bb < 2; bb++) {
                int b = bid * 2 + bb;
                float m = -1e30f;
                for (int s = tid; s < SS; s += TPB) m = fmaxf(m, g_sc[b * SS + s]);
                sm[tid] = m; __syncthreads();
                for (int off = TPB / 2; off > 0; off >>= 1) {
                    if (tid < off) sm[tid] = fmaxf(sm[tid], sm[tid + off]);
                    __syncthreads();
                }
                m = sm[0]; __syncthreads();
                float sum = 0.f;
                for (int s = tid; s < SS; s += TPB) {
                    float e = __expf(g_sc[b * SS + s] - m);
                    g_wsm[b * SS + s] = e;
                    sum += e;
                }
                sm[tid] = sum; __syncthreads();
                for (int off = TPB / 2; off > 0; off >>= 1) {
                    if (tid < off) sm[tid] += sm[tid + off];
                    __syncthreads();
                }
                float inv = 1.f / sm[0]; __syncthreads();
                for (int s = tid; s < SS; s += TPB) g_wsm[b * SS + s] *= inv;
            }
        }
        grid_barrier();

        // D: context -> xcat[:,1:513]; xcat[:,0] = dec_in — 2 b per block
        {
#pragma unroll 1
            for (int bb = 0; bb < 2; bb++) {
                int b = bid * 2 + bb;
                for (int i = tid; i < SS; i += TPB) sm[i] = g_wsm[b * SS + i];
                __syncthreads();
                const float* base = g_enc_outs + (size_t)b * SS * HH;
                float a0 = 0.f, a1 = 0.f;
#pragma unroll 4
                for (int s = 0; s < SS; s++) {
                    const float* r = base + (size_t)s * HH;
                    a0 += sm[s] * r[tid];
                    a1 += sm[s] * r[tid + 256];
                }
                g_xcat[b * 513 + 1 + tid] = a0;
                g_xcat[b * 513 + 1 + tid + 256] = a1;
                if (tid == 0) g_xcat[b * 513] = g_decin[b];
                __syncthreads();
            }
        }
        grid_barrier();

        // E: decoder LSTM layer 0 (K = 513 + 512)
        gemm_lstm_tile(tn, tm, g_xcat, 513, 513,
                       g_h0[p], HH, HH, g_Wd0, 1025, g_bd0,
                       g_c0, g_h0[p ^ 1], nullptr, 0, raw);
        grid_barrier();

        // F: decoder LSTM layer 1 (K = 1024)
        gemm_lstm_tile(tn, tm, g_h0[p ^ 1], HH, HH,
                       g_h1[p], HH, HH, g_Wd1, 1024, g_bd1,
                       g_c1, g_h1[p ^ 1], nullptr, 0, raw);
        grid_barrier();

        // G: pred + decin update (32 blocks x 8 warps = 256 b)
        if (bid < 32) {
            int warp = tid >> 5, lane = tid & 31;
            int b = bid * 8 + warp;
            const float* h1r = g_h1[p ^ 1] + b * HH;
            float acc = 0.f;
            for (int h = lane; h < HH; h += 32) acc += h1r[h] * fc_W[h];
#pragma unroll
            for (int off = 16; off > 0; off >>= 1)
                acc += __shfl_down_sync(0xffffffffu, acc, off);
            if (lane == 0) {
                float pred = acc + fc_b[0];
                out[b * PLEN + it] = pred;
                g_decin[b] = 0.8f * pred + 0.2f * g_hist[b];
            }
        }
        // no barrier needed here: the barrier after next step's stage A orders
        // G(t)'s decin write before D(t+1)'s read; dp overwrite in A(t+1) is
        // ordered after B(t) by the C/D/E/F barriers of step t.
    }
}

// ---------------- launch ----------------
extern "C" void kernel_launch(void* const* d_in, const int* in_sizes, int n_in,
                              void* d_out, int out_size) {
    (void)in_sizes; (void)n_in; (void)out_size;
    const float* src    = (const float*)d_in[0];
    const float* ew0    = (const float*)d_in[1];
    const float* eu0    = (const float*)d_in[2];
    const float* ebi0   = (const float*)d_in[3];
    const float* ebh0   = (const float*)d_in[4];
    const float* ew1    = (const float*)d_in[5];
    const float* eu1    = (const float*)d_in[6];
    const float* ebi1   = (const float*)d_in[7];
    const float* ebh1   = (const float*)d_in[8];
    const float* dw0    = (const float*)d_in[9];
    const float* du0    = (const float*)d_in[10];
    const float* dbi0   = (const float*)d_in[11];
    const float* dbh0   = (const float*)d_in[12];
    const float* dw1    = (const float*)d_in[13];
    const float* du1    = (const float*)d_in[14];
    const float* dbi1   = (const float*)d_in[15];
    const float* dbh1   = (const float*)d_in[16];
    const float* attn_W = (const float*)d_in[17];
    const float* attn_b = (const float*)d_in[18];
    const float* v_W    = (const float*)d_in[19];
    const float* fc_W   = (const float*)d_in[20];
    const float* fc_b   = (const float*)d_in[21];
    float* out = (float*)d_out;

    prep_all<<<2048, 256>>>(src, ew0, eu0, ebi0, ebh0, ew1, eu1, ebi1, ebh1,
                            dw0, du0, dbi0, dbh0, dw1, du1, dbi1, dbh1);
    mega<<<NB, TPB>>>(src, attn_W, attn_b, v_W, fc_W, fc_b, out);
}

// round 8
// speedup vs baseline: 2.0095x; 1.1416x over previous
#include <cuda_runtime.h>
#include <mma.h>
#include <math.h>

using namespace nvcuda;

#define BB 256
#define SS 512
#define DD 32
#define HH 512
#define GG 2048   // 4*HH
#define PLEN 24
#define NB 128    // persistent blocks (<=148 SMs -> all co-resident)
#define TPB 512   // threads per block (16 warps)

// ---------------- scratch (__device__ globals; no allocation) ----------------
__device__ float g_enc_outs[BB * SS * HH];          // 268 MB
__device__ float g_enc_proj[BB * SS * HH];          // 268 MB
__device__ float g_h0[2][BB * HH];
__device__ float g_h1[2][BB * HH];
__device__ float g_c0[BB * HH];
__device__ float g_c1[BB * HH];
__device__ float g_W0[GG * 544];                    // [ew0 | eu0], gate-interleaved rows
__device__ float g_W1[GG * 1024];                   // [ew1 | eu1]
__device__ float g_Wd0[GG * 1025];                  // [dw0 | du0]
__device__ float g_Wd1[GG * 1024];                  // [dw1 | du1]
__device__ float g_b0[GG], g_b1[GG], g_bd0[GG], g_bd1[GG];
__device__ float g_dp[BB * HH];
__device__ float g_sc[BB * SS];
__device__ float g_wsm[BB * SS];
__device__ float g_xcat[BB * 513];
__device__ float g_decin[BB];
__device__ float g_hist[BB];

// grid-wide barrier state
__device__ unsigned int g_bar_count = 0;
__device__ volatile unsigned int g_bar_gen = 0;

__device__ __forceinline__ void grid_barrier() {
    __syncthreads();
    if (threadIdx.x == 0) {
        __threadfence();
        unsigned int gen = g_bar_gen;
        if (atomicAdd(&g_bar_count, 1u) == NB - 1u) {
            g_bar_count = 0;
            __threadfence();
            g_bar_gen = gen + 1u;
        } else {
            while (g_bar_gen == gen) { __nanosleep(32); }
        }
        __threadfence();
    }
    __syncthreads();
}

__device__ __forceinline__ float fast_tanh(float x) {
    float y;
    asm("tanh.approx.f32 %0, %1;" : "=f"(y) : "f"(x));
    return y;
}
__device__ __forceinline__ float sigf(float x) {
    return __fdividef(1.f, 1.f + __expf(-x));
}
__device__ __forceinline__ float tanhg(float x) {
    return 1.f - __fdividef(2.f, __expf(2.f * x) + 1.f);
}
__device__ __forceinline__ float to_tf32(float x) {
    float y;
    asm("cvt.rna.tf32.f32 %0, %1;" : "=f"(y) : "f"(x));
    return y;
}

// ---------------- fused prep: interleave weights, biases, init state ---------
// n' = 4j+q maps to original row n = q*HH + j.
__device__ __forceinline__ void interleave_region(
    float* __restrict__ dst, const float* __restrict__ Wa, int Ka,
    const float* __restrict__ Wb, int Kb, int base, int stride) {
    int Kt = Ka + Kb;
    int total = GG * Kt;
    for (int idx = base; idx < total; idx += stride) {
        int np = idx / Kt;
        int k = idx - np * Kt;
        int q = np & 3;
        int j = np >> 2;
        int n = q * HH + j;
        float v;
        if (k < Ka) v = Wa[(size_t)n * Ka + k];
        else        v = Wb[(size_t)n * Kb + (k - Ka)];
        dst[idx] = v;
    }
}

__global__ void prep_all(
    const float* __restrict__ src,
    const float* __restrict__ ew0, const float* __restrict__ eu0,
    const float* __restrict__ ebi0, const float* __restrict__ ebh0,
    const float* __restrict__ ew1, const float* __restrict__ eu1,
    const float* __restrict__ ebi1, const float* __restrict__ ebh1,
    const float* __restrict__ dw0, const float* __restrict__ du0,
    const float* __restrict__ dbi0, const float* __restrict__ dbh0,
    const float* __restrict__ dw1, const float* __restrict__ du1,
    const float* __restrict__ dbi1, const float* __restrict__ dbh1)
{
    int base = blockIdx.x * blockDim.x + threadIdx.x;
    int stride = gridDim.x * blockDim.x;

    interleave_region(g_W0, ew0, DD, eu0, HH, base, stride);
    interleave_region(g_W1, ew1, HH, eu1, HH, base, stride);
    interleave_region(g_Wd0, dw0, HH + 1, du0, HH, base, stride);
    interleave_region(g_Wd1, dw1, HH, du1, HH, base, stride);

    for (int np = base; np < GG; np += stride) {
        int q = np & 3;
        int j = np >> 2;
        int n = q * HH + j;
        g_b0[np] = ebi0[n] + ebh0[n];
        g_b1[np] = ebi1[n] + ebh1[n];
        g_bd0[np] = dbi0[n] + dbh0[n];
        g_bd1[np] = dbi1[n] + dbh1[n];
    }
    for (int i = base; i < BB * HH; i += stride) {
        g_h0[0][i] = 0.f; g_h1[0][i] = 0.f; g_c0[i] = 0.f; g_c1[i] = 0.f;
    }
    for (int i = base; i < BB; i += stride) {
        size_t o = (size_t)i * SS * DD + (size_t)(SS - 1) * DD;
        g_decin[i] = src[o + (DD - 1)];   // src[:, -1, -1]
        g_hist[i]  = src[o + (DD - 15)];  // src[:, -1, -15]
    }
}

// ---------------- wmma tf32 GEMM core -----------------------------------------
// Tile 64(m) x 64(n), K chunks of 32, double-buffered smem, ONE sync per chunk.
// 16 warps: 4(m) x 2(n) x 2(k-split). Each warp -> two 16x16 acc frags over
// HALF the k8 sub-steps of each chunk. Two partial C tiles are summed in the
// epilogue.
// smem_raw (floats): A buf0 [0,2304) | A buf1 [2304,4608)
//                    W buf0 [4608,6912) | W buf1 [6912,9216)
// C partials alias after compute: Cs0 @ 0 (64x68), Cs1 @ 4608 (64x68).
typedef wmma::fragment<wmma::matrix_a, 16, 16, 8, wmma::precision::tf32, wmma::row_major> AFrag;
typedef wmma::fragment<wmma::matrix_b, 16, 16, 8, wmma::precision::tf32, wmma::col_major> BFrag;
typedef wmma::fragment<wmma::accumulator, 16, 16, 8, float> CFrag;

__device__ __forceinline__ void gemm_core_tf32(
    int bn, int bm,
    const float* __restrict__ A1, int lda1, int K1,
    const float* __restrict__ A2, int lda2, int K2,
    const float* __restrict__ W, int ldw,
    float* __restrict__ smem_raw)
{
    const int tid = threadIdx.x;
    const int warp = tid >> 5;
    const int wm = warp & 3;          // 0..3 -> 16-row group
    const int wn = (warp >> 2) & 1;   // 0..1 -> 32-col group
    const int wk = warp >> 3;         // 0..1 -> k8 half
    const int Kt = K1 + K2;
    const int nck = (Kt + 31) >> 5;
    const int row = tid >> 5;         // load row base (16 rows apart per t)
    const int kk = tid & 31;

    CFrag acc[2];
    wmma::fill_fragment(acc[0], 0.f);
    wmma::fill_fragment(acc[1], 0.f);

    float ra[4], rw[4];

#define PREF(K0)                                                               \
    {                                                                          \
        int gk = (K0) + kk;                                                    \
        _Pragma("unroll")                                                      \
        for (int t = 0; t < 4; t++) {                                          \
            int r = row + t * 16;                                              \
            float va = 0.f;                                                    \
            int m = bm + r;                                                    \
            if (gk < K1)      va = A1[(size_t)m * lda1 + gk];                  \
            else if (gk < Kt) va = A2[(size_t)m * lda2 + (gk - K1)];           \
            ra[t] = to_tf32(va);                                               \
            int n = bn + r;                                                    \
            rw[t] = (gk < Kt) ? to_tf32(W[(size_t)n * ldw + gk]) : 0.f;        \
        }                                                                      \
    }

#define STORE(BUF)                                                             \
    {                                                                          \
        float* Ab = smem_raw + (BUF) * 2304;                                   \
        float* Wb = smem_raw + 4608 + (BUF) * 2304;                            \
        _Pragma("unroll")                                                      \
        for (int t = 0; t < 4; t++) {                                          \
            int r = row + t * 16;                                              \
            Ab[r * 36 + kk] = ra[t];                                           \
            Wb[r * 36 + kk] = rw[t];                                           \
        }                                                                      \
    }

    PREF(0);
    STORE(0);
    __syncthreads();
    int buf = 0;

    for (int ck = 0; ck < nck; ck++) {
        if (ck + 1 < nck) PREF((ck + 1) << 5);
        const float* Ab = smem_raw + buf * 2304;
        const float* Wb = smem_raw + 4608 + buf * 2304;
#pragma unroll
        for (int kh = 0; kh < 2; kh++) {
            int k8 = wk * 2 + kh;
            AFrag af;
            wmma::load_matrix_sync(af, &Ab[(wm * 16) * 36 + k8 * 8], 36);
            BFrag bf0, bf1;
            wmma::load_matrix_sync(bf0, &Wb[(wn * 32) * 36 + k8 * 8], 36);
            wmma::load_matrix_sync(bf1, &Wb[(wn * 32 + 16) * 36 + k8 * 8], 36);
            wmma::mma_sync(acc[0], af, bf0, acc[0]);
            wmma::mma_sync(acc[1], af, bf1, acc[1]);
        }
        if (ck + 1 < nck) {
            buf ^= 1;
            STORE(buf);
            __syncthreads();
        }
    }
#undef PREF
#undef STORE

    __syncthreads();   // all mma smem reads done before aliasing C onto raw
    float* Cbase = smem_raw + wk * 4608;      // Cs0 @ 0, Cs1 @ 4608
    wmma::store_matrix_sync(Cbase + (wm * 16) * 68 + wn * 32, acc[0], 68, wmma::mem_row_major);
    wmma::store_matrix_sync(Cbase + (wm * 16) * 68 + wn * 32 + 16, acc[1], 68, wmma::mem_row_major);
    __syncthreads();
}

// ---------------- tile GEMM + fused LSTM cell ----------------
__device__ __forceinline__ void gemm_lstm_tile(
    int tn, int tm,
    const float* __restrict__ A1, int lda1, int K1,
    const float* __restrict__ A2, int lda2, int K2,
    const float* __restrict__ W, int ldw,
    const float* __restrict__ bias,
    float* __restrict__ c_state,
    float* __restrict__ h_out,
    float* __restrict__ h_extra, size_t extra_stride,
    float* __restrict__ smem_raw)
{
    const int bn = tn * 64;
    const int bm = tm * 64;
    gemm_core_tf32(bn, bm, A1, lda1, K1, A2, lda2, K2, W, ldw, smem_raw);
    const float* C0 = smem_raw;
    const float* C1 = smem_raw + 4608;

    const int tid = threadIdx.x;
    // 64 rows x 16 gate-quads = 1024 work items
#pragma unroll
    for (int t = 0; t < 2; t++) {
        int idx = tid + t * TPB;
        int r = idx >> 4;          // row in tile (batch)
        int jj = idx & 15;         // gate-quad within tile
        int b = bm + r;
        int ncol = bn + 4 * jj;
        int j = ncol >> 2;
        int o = r * 68 + 4 * jj;
        float gi = sigf(C0[o + 0] + C1[o + 0] + bias[ncol + 0]);
        float gf = sigf(C0[o + 1] + C1[o + 1] + bias[ncol + 1]);
        float gg = tanhg(C0[o + 2] + C1[o + 2] + bias[ncol + 2]);
        float go = sigf(C0[o + 3] + C1[o + 3] + bias[ncol + 3]);
        float c = gf * c_state[b * HH + j] + gi * gg;
        c_state[b * HH + j] = c;
        float h = go * tanhg(c);
        h_out[b * HH + j] = h;
        if (h_extra) h_extra[(size_t)b * extra_stride + j] = h;
    }
    __syncthreads();
}

// ---------------- plain tile GEMM: C[m,n] = sum_k A[m,k]*W[n,k] (+bias) ------
__device__ __forceinline__ void gemm_bias_tile(
    int tn, int tm,
    const float* __restrict__ A, int lda,
    const float* __restrict__ W, int ldw,
    const float* __restrict__ bias,
    float* __restrict__ C, int N, int K,
    float* __restrict__ smem_raw)
{
    const int bn = tn * 64;
    const int bm = tm * 64;
    gemm_core_tf32(bn, bm, A, lda, K, (const float*)0, 0, 0, W, ldw, smem_raw);
    const float* C0 = smem_raw;
    const float* C1 = smem_raw + 4608;

    const int tid = threadIdx.x;
#pragma unroll
    for (int t = 0; t < 2; t++) {
        int idx = tid + t * TPB;
        int r = idx >> 4;
        int c4 = idx & 15;
        int m = bm + r;
        int n = bn + 4 * c4;
        int o = r * 68 + 4 * c4;
        float4 v0 = *(const float4*)&C0[o];
        float4 v1 = *(const float4*)&C1[o];
        float4 v = make_float4(v0.x + v1.x, v0.y + v1.y, v0.z + v1.z, v0.w + v1.w);
        if (bias) {
            float4 bv = *(const float4*)&bias[n];
            v.x += bv.x; v.y += bv.y; v.z += bv.z; v.w += bv.w;
        }
        *(float4*)&C[(size_t)m * N + n] = v;
    }
    __syncthreads();
}

// ---------------- persistent mega-kernel ----------------
__global__ __launch_bounds__(TPB) void mega(
    const float* __restrict__ src,
    const float* __restrict__ attn_W,
    const float* __restrict__ attn_b,
    const float* __restrict__ v_W,
    const float* __restrict__ fc_W,
    const float* __restrict__ fc_b,
    float* __restrict__ out)
{
    __shared__ __align__(16) float raw[9216];   // A/W double buffers; C aliases
    __shared__ float sm[1024];

    const int bid = blockIdx.x;
    const int tid = threadIdx.x;
    const int tn = bid & 31;   // 32 n-tiles (N=2048)
    const int tm = bid >> 5;   // 4 m-tiles  (M=256)

    // ---------------- encoder: 512 steps, ONE grid barrier per step ----------------
    for (int t = 0; t < SS; t++) {
        int p = t & 1;
        gemm_lstm_tile(tn, tm, src + t * DD, SS * DD, DD,
                       g_h0[p], HH, HH, g_W0, 544, g_b0,
                       g_c0, g_h0[p ^ 1], nullptr, 0, raw);
        grid_barrier();  // h0(t) complete; L1(t) and L0(t+1) are conflict-free after
        gemm_lstm_tile(tn, tm, g_h0[p ^ 1], HH, HH,
                       g_h1[p], HH, HH, g_W1, 1024, g_b1,
                       g_c1, g_h1[p ^ 1],
                       g_enc_outs + (size_t)t * HH, (size_t)SS * HH, raw);
    }
    grid_barrier();  // enc_outs + final states complete

    // ---------------- enc_proj = enc_outs @ W_enc^T + attn_b ----------------
    // tiles: (BB*SS/64) x (HH/64) = 2048 x 8 = 16384
    for (int tt = bid; tt < 16384; tt += NB) {
        gemm_bias_tile(tt & 7, tt >> 3, g_enc_outs, HH, attn_W, 2 * HH,
                       attn_b, g_enc_proj, HH, HH, raw);
    }
    grid_barrier();

    // ---------------- decoder: 24 steps ----------------
    for (int it = 0; it < PLEN; it++) {
        int p = it & 1;

        // A: dp = h1 @ W_dec^T   (8 x 4 = 32 tiles)
        if (bid < 32) {
            gemm_bias_tile(bid & 7, bid >> 3, g_h1[p], HH, attn_W + HH, 2 * HH,
                           nullptr, g_dp, HH, HH, raw);
        }
        grid_barrier();

        // B: scores[b,s] = sum_h v[h]*tanh(ep[b,s,h]+dp[b,h]) — 2 b per block
        {
            int warp = tid >> 5, lane = tid & 31;
#pragma unroll 1
            for (int bb = 0; bb < 2; bb++) {
                int b = bid * 2 + bb;
                for (int i = tid; i < HH; i += TPB) {
                    sm[i] = g_dp[b * HH + i];
                    sm[512 + i] = v_W[i];
                }
                __syncthreads();
                const float* ep = g_enc_proj + (size_t)b * SS * HH;
                for (int s = warp; s < SS; s += 16) {
                    const float* row = ep + (size_t)s * HH;
                    float acc = 0.f;
#pragma unroll
                    for (int h0 = 0; h0 < 4; h0++) {
                        int h = h0 * 128 + lane * 4;
                        float4 r = *(const float4*)&row[h];
                        float4 d = *(const float4*)&sm[h];
                        float4 v = *(const float4*)&sm[512 + h];
                        acc += v.x * fast_tanh(r.x + d.x)
                             + v.y * fast_tanh(r.y + d.y)
                             + v.z * fast_tanh(r.z + d.z)
                             + v.w * fast_tanh(r.w + d.w);
                    }
#pragma unroll
                    for (int off = 16; off > 0; off >>= 1)
                        acc += __shfl_down_sync(0xffffffffu, acc, off);
                    if (lane == 0) g_sc[b * SS + s] = acc;
                }
                __syncthreads();
            }
        }
        grid_barrier();

        // C: softmax over s — 2 b per block
        {
#pragma unroll 1
            for (int bb = 0; bb < 2; bb++) {
                int b = bid * 2 + bb;
                float m = -1e30f;
                for (int s = tid; s < SS; s += TPB) m = fmaxf(m, g_sc[b * SS + s]);
                sm[tid] = m; __syncthreads();
                for (int off = TPB / 2; off > 0; off >>= 1) {
                    if (tid < off) sm[tid] = fmaxf(sm[tid], sm[tid + off]);
                    __syncthreads();
                }
                m = sm[0]; __syncthreads();
                float sum = 0.f;
                for (int s = tid; s < SS; s += TPB) {
                    float e = __expf(g_sc[b * SS + s] - m);
                    g_wsm[b * SS + s] = e;
                    sum += e;
                }
                sm[tid] = sum; __syncthreads();
                for (int off = TPB / 2; off > 0; off >>= 1) {
                    if (tid < off) sm[tid] += sm[tid + off];
                    __syncthreads();
                }
                float inv = 1.f / sm[0]; __syncthreads();
                for (int s = tid; s < SS; s += TPB) g_wsm[b * SS + s] *= inv;
            }
        }
        grid_barrier();

        // D: context -> xcat[:,1:513]; xcat[:,0] = dec_in — 2 b per block,
        // one h column per thread (TPB == HH)
        {
#pragma unroll 1
            for (int bb = 0; bb < 2; bb++) {
                int b = bid * 2 + bb;
                for (int i = tid; i < SS; i += TPB) sm[i] = g_wsm[b * SS + i];
                __syncthreads();
                const float* base = g_enc_outs + (size_t)b * SS * HH;
                float a0 = 0.f;
#pragma unroll 4
                for (int s = 0; s < SS; s++) {
                    a0 += sm[s] * base[(size_t)s * HH + tid];
                }
                g_xcat[b * 513 + 1 + tid] = a0;
                if (tid == 0) g_xcat[b * 513] = g_decin[b];
                __syncthreads();
            }
        }
        grid_barrier();

        // E: decoder LSTM layer 0 (K = 513 + 512)
        gemm_lstm_tile(tn, tm, g_xcat, 513, 513,
                       g_h0[p], HH, HH, g_Wd0, 1025, g_bd0,
                       g_c0, g_h0[p ^ 1], nullptr, 0, raw);
        grid_barrier();

        // F: decoder LSTM layer 1 (K = 1024)
        gemm_lstm_tile(tn, tm, g_h0[p ^ 1], HH, HH,
                       g_h1[p], HH, HH, g_Wd1, 1024, g_bd1,
                       g_c1, g_h1[p ^ 1], nullptr, 0, raw);
        grid_barrier();

        // G: pred + decin update (16 blocks x 16 warps = 256 b)
        if (bid < 16) {
            int warp = tid >> 5, lane = tid & 31;
            int b = bid * 16 + warp;
            const float* h1r = g_h1[p ^ 1] + b * HH;
            float acc = 0.f;
            for (int h = lane; h < HH; h += 32) acc += h1r[h] * fc_W[h];
#pragma unroll
            for (int off = 16; off > 0; off >>= 1)
                acc += __shfl_down_sync(0xffffffffu, acc, off);
            if (lane == 0) {
                float pred = acc + fc_b[0];
                out[b * PLEN + it] = pred;
                g_decin[b] = 0.8f * pred + 0.2f * g_hist[b];
            }
        }
        // no barrier needed here: the barrier after next step's stage A orders
        // G(t)'s decin write before D(t+1)'s read; dp overwrite in A(t+1) is
        // ordered after B(t) by the C/D/E/F barriers of step t.
    }
}

// ---------------- launch ----------------
extern "C" void kernel_launch(void* const* d_in, const int* in_sizes, int n_in,
                              void* d_out, int out_size) {
    (void)in_sizes; (void)n_in; (void)out_size;
    const float* src    = (const float*)d_in[0];
    const float* ew0    = (const float*)d_in[1];
    const float* eu0    = (const float*)d_in[2];
    const float* ebi0   = (const float*)d_in[3];
    const float* ebh0   = (const float*)d_in[4];
    const float* ew1    = (const float*)d_in[5];
    const float* eu1    = (const float*)d_in[6];
    const float* ebi1   = (const float*)d_in[7];
    const float* ebh1   = (const float*)d_in[8];
    const float* dw0    = (const float*)d_in[9];
    const float* du0    = (const float*)d_in[10];
    const float* dbi0   = (const float*)d_in[11];
    const float* dbh0   = (const float*)d_in[12];
    const float* dw1    = (const float*)d_in[13];
    const float* du1    = (const float*)d_in[14];
    const float* dbi1   = (const float*)d_in[15];
    const float* dbh1   = (const float*)d_in[16];
    const float* attn_W = (const float*)d_in[17];
    const float* attn_b = (const float*)d_in[18];
    const float* v_W    = (const float*)d_in[19];
    const float* fc_W   = (const float*)d_in[20];
    const float* fc_b   = (const float*)d_in[21];
    float* out = (float*)d_out;

    prep_all<<<2048, 256>>>(src, ew0, eu0, ebi0, ebh0, ew1, eu1, ebi1, ebh1,
                            dw0, du0, dbi0, dbh0, dw1, du1, dbi1, dbh1);
    mega<<<NB, TPB>>>(src, attn_W, attn_b, v_W, fc_W, fc_b, out);
}

// round 12
// speedup vs baseline: 2.6677x; 1.3275x over previous
#include <cuda_runtime.h>
#include <mma.h>
#include <math.h>
#include <stdint.h>

using namespace nvcuda;

#define BB 256
#define SS 512
#define DD 32
#define HH 512
#define GG 2048   // 4*HH
#define PLEN 24
#define NB 128    // persistent blocks (<=148 SMs -> all co-resident)
#define TPB 512   // threads per block (16 warps)

#define XS 544    // xcat padded stride (544 = 17*32, 16B aligned)
#define WD0K 1056 // Wd0 padded K (544 + 512)

// ---------------- scratch (__device__ globals; no allocation) ----------------
__device__ float g_enc_outs[BB * SS * HH];          // FULL fp32 h (stage D reads)
__device__ float g_enc_outs_r[BB * SS * HH];        // tf32-rounded h (enc_proj GEMM)
__device__ float g_enc_proj[BB * SS * HH];          // full fp32
__device__ float g_srcr[BB * SS * DD];              // tf32-rounded src copy
__device__ float g_attnW[HH * 2 * HH];              // tf32-rounded attn_W copy
__device__ float g_h0[2][BB * HH];                  // rounded (GEMM operand)
__device__ float g_h1[2][BB * HH];                  // rounded (GEMM operand)
__device__ float g_h1f[BB * HH];                    // FULL fp32 decoder h1 (stage G)
__device__ float g_c0[BB * HH];
__device__ float g_c1[BB * HH];
__device__ float g_W0[GG * 544];                    // [ew0 | eu0], gate-interleaved, tf32
__device__ float g_W1[GG * 1024];                   // [ew1 | eu1], tf32
__device__ float g_Wd0[GG * WD0K];                  // [dw0 | pad | du0], tf32
__device__ float g_Wd1[GG * 1024];                  // [dw1 | du1], tf32
__device__ float g_b0[GG], g_b1[GG], g_bd0[GG], g_bd1[GG];
__device__ float g_dp[BB * HH];
__device__ float g_sc[BB * SS];
__device__ float g_wsm[BB * SS];
__device__ float g_xcat[BB * XS];                   // col0=dec_in, 1..512=ctx, 513..543=0
__device__ float g_decin[BB];
__device__ float g_hist[BB];

// grid-wide barrier state
__device__ unsigned int g_bar_count = 0;
__device__ volatile unsigned int g_bar_gen = 0;

__device__ __forceinline__ void grid_barrier() {
    __syncthreads();
    if (threadIdx.x == 0) {
        __threadfence();
        unsigned int gen = g_bar_gen;
        if (atomicAdd(&g_bar_count, 1u) == NB - 1u) {
            g_bar_count = 0;
            __threadfence();
            g_bar_gen = gen + 1u;
        } else {
            while (g_bar_gen == gen) { __nanosleep(32); }
        }
        __threadfence();
    }
    __syncthreads();
}

__device__ __forceinline__ float fast_tanh(float x) {
    float y;
    asm("tanh.approx.f32 %0, %1;" : "=f"(y) : "f"(x));
    return y;
}
__device__ __forceinline__ float sigf(float x) {
    return __fdividef(1.f, 1.f + __expf(-x));
}
__device__ __forceinline__ float tanhg(float x) {
    return 1.f - __fdividef(2.f, __expf(2.f * x) + 1.f);
}
__device__ __forceinline__ float to_tf32(float x) {
    float y;
    asm("cvt.rna.tf32.f32 %0, %1;" : "=f"(y) : "f"(x));
    return y;
}

__device__ __forceinline__ void cp16(uint32_t dst, const float* src) {
    asm volatile("cp.async.cg.shared.global [%0], [%1], 16;" :: "r"(dst), "l"(src));
}
#define CP_COMMIT() asm volatile("cp.async.commit_group;")
#define CP_WAIT2()  asm volatile("cp.async.wait_group 2;")

// ---------------- fused prep ----------------
// n' = 4j+q maps to original row n = q*HH + j. Weights stored tf32-rounded.
__device__ __forceinline__ void interleave_region(
    float* __restrict__ dst, const float* __restrict__ Wa, int Ka,
    const float* __restrict__ Wb, int Kb, int base, int stride) {
    int Kt = Ka + Kb;
    int total = GG * Kt;
    for (int idx = base; idx < total; idx += stride) {
        int np = idx / Kt;
        int k = idx - np * Kt;
        int q = np & 3;
        int j = np >> 2;
        int n = q * HH + j;
        float v;
        if (k < Ka) v = Wa[(size_t)n * Ka + k];
        else        v = Wb[(size_t)n * Kb + (k - Ka)];
        dst[idx] = to_tf32(v);
    }
}

// Wd0: cols [0,513) = dw0, [513,544) = 0, [544,1056) = du0
__device__ __forceinline__ void interleave_pad_wd0(
    float* __restrict__ dst, const float* __restrict__ Wa,
    const float* __restrict__ Wb, int base, int stride) {
    int total = GG * WD0K;
    for (int idx = base; idx < total; idx += stride) {
        int np = idx / WD0K;
        int k = idx - np * WD0K;
        int q = np & 3;
        int j = np >> 2;
        int n = q * HH + j;
        float v = 0.f;
        if (k < 513)      v = Wa[(size_t)n * 513 + k];
        else if (k >= XS) v = Wb[(size_t)n * HH + (k - XS)];
        dst[idx] = to_tf32(v);
    }
}

__global__ void prep_all(
    const float* __restrict__ src,
    const float* __restrict__ ew0, const float* __restrict__ eu0,
    const float* __restrict__ ebi0, const float* __restrict__ ebh0,
    const float* __restrict__ ew1, const float* __restrict__ eu1,
    const float* __restrict__ ebi1, const float* __restrict__ ebh1,
    const float* __restrict__ dw0, const float* __restrict__ du0,
    const float* __restrict__ dbi0, const float* __restrict__ dbh0,
    const float* __restrict__ dw1, const float* __restrict__ du1,
    const float* __restrict__ dbi1, const float* __restrict__ dbh1,
    const float* __restrict__ attn_W)
{
    int base = blockIdx.x * blockDim.x + threadIdx.x;
    int stride = gridDim.x * blockDim.x;

    interleave_region(g_W0, ew0, DD, eu0, HH, base, stride);
    interleave_region(g_W1, ew1, HH, eu1, HH, base, stride);
    interleave_pad_wd0(g_Wd0, dw0, du0, base, stride);
    interleave_region(g_Wd1, dw1, HH, du1, HH, base, stride);

    for (int i = base; i < HH * 2 * HH; i += stride) g_attnW[i] = to_tf32(attn_W[i]);
    for (int i = base; i < BB * SS * DD; i += stride) g_srcr[i] = to_tf32(src[i]);

    for (int np = base; np < GG; np += stride) {
        int q = np & 3;
        int j = np >> 2;
        int n = q * HH + j;
        g_b0[np] = ebi0[n] + ebh0[n];
        g_b1[np] = ebi1[n] + ebh1[n];
        g_bd0[np] = dbi0[n] + dbh0[n];
        g_bd1[np] = dbi1[n] + dbh1[n];
    }
    for (int i = base; i < BB * HH; i += stride) {
        g_h0[0][i] = 0.f; g_h1[0][i] = 0.f; g_c0[i] = 0.f; g_c1[i] = 0.f;
    }
    for (int i = base; i < BB * XS; i += stride) g_xcat[i] = 0.f;
    for (int i = base; i < BB; i += stride) {
        size_t o = (size_t)i * SS * DD + (size_t)(SS - 1) * DD;
        g_decin[i] = src[o + (DD - 1)];   // src[:, -1, -1]
        g_hist[i]  = src[o + (DD - 15)];  // src[:, -1, -15]
    }
}

// ---------------- wmma tf32 GEMM core, cp.async 4-stage pipeline --------------
// Tile 64(m) x 64(n). K chunks of 32 (ALL K's are multiples of 32; A1/A2 split
// is chunk-aligned). 16 warps: 4(m) x 2(n) x 2(k-split); partial C tiles summed
// in the epilogue. Operands in memory are pre-rounded to tf32 -> no cvt here.
// dyn smem (floats): 4 stages x (A 64x36 | W 64x36) = 4 x 4608.
// C partials alias stages 0/1 after drain: C0 @ 0, C1 @ 4608 (64x68 each).
typedef wmma::fragment<wmma::matrix_a, 16, 16, 8, wmma::precision::tf32, wmma::row_major> AFrag;
typedef wmma::fragment<wmma::matrix_b, 16, 16, 8, wmma::precision::tf32, wmma::col_major> BFrag;
typedef wmma::fragment<wmma::accumulator, 16, 16, 8, float> CFrag;

__device__ __forceinline__ void gemm_core_tf32(
    int bn, int bm,
    const float* __restrict__ A1, int lda1, int K1,
    const float* __restrict__ A2, int lda2, int K2,
    const float* __restrict__ W, int ldw,
    float* __restrict__ smem)
{
    const int tid = threadIdx.x;
    const int warp = tid >> 5;
    const int wm = warp & 3;          // 16-row group
    const int wn = (warp >> 2) & 1;   // 32-col group
    const int wk = warp >> 3;         // k8 half
    const int nck = (K1 + K2) >> 5;
    const int row = tid >> 3;         // 0..63
    const int seg = tid & 7;          // 0..7 (16B segment within 32-col chunk)
    const uint32_t sbase = (uint32_t)__cvta_generic_to_shared(smem);
    const uint32_t dA = sbase + (uint32_t)(row * 36 + seg * 4) * 4u;

    CFrag acc[2];
    wmma::fill_fragment(acc[0], 0.f);
    wmma::fill_fragment(acc[1], 0.f);

#define ISSUE(CK)                                                              \
    {                                                                          \
        int k0 = (CK) << 5;                                                    \
        const float* sA = (k0 < K1)                                            \
            ? (A1 + (size_t)(bm + row) * lda1 + k0 + seg * 4)                  \
            : (A2 + (size_t)(bm + row) * lda2 + (k0 - K1) + seg * 4);          \
        const float* sW = W + (size_t)(bn + row) * ldw + k0 + seg * 4;         \
        uint32_t dd = dA + (uint32_t)(((CK) & 3) * 4608) * 4u;                 \
        cp16(dd, sA);                                                          \
        cp16(dd + 2304u * 4u, sW);                                             \
    }

    ISSUE(0); CP_COMMIT();
    ISSUE(1); CP_COMMIT();
    ISSUE(2); CP_COMMIT();

    for (int ck = 0; ck < nck; ck++) {
        CP_WAIT2();          // group ck complete (own copies)
        __syncthreads();     // publish all threads' copies; also guards reuse
        if (ck + 3 < nck) ISSUE(ck + 3);
        CP_COMMIT();         // always commit (empty groups keep count uniform)
        const float* Ab = smem + (ck & 3) * 4608;
        const float* Wb = Ab + 2304;
#pragma unroll
        for (int kh = 0; kh < 2; kh++) {
            int k8 = wk * 2 + kh;
            AFrag af;
            wmma::load_matrix_sync(af, &Ab[(wm * 16) * 36 + k8 * 8], 36);
            BFrag bf0, bf1;
            wmma::load_matrix_sync(bf0, &Wb[(wn * 32) * 36 + k8 * 8], 36);
            wmma::load_matrix_sync(bf1, &Wb[(wn * 32 + 16) * 36 + k8 * 8], 36);
            wmma::mma_sync(acc[0], af, bf0, acc[0]);
            wmma::mma_sync(acc[1], af, bf1, acc[1]);
        }
    }
#undef ISSUE

    __syncthreads();   // all mma smem reads done before aliasing C onto stages
    float* Cb = smem + wk * 4608;      // C0 @ 0, C1 @ 4608
    wmma::store_matrix_sync(Cb + (wm * 16) * 68 + wn * 32, acc[0], 68, wmma::mem_row_major);
    wmma::store_matrix_sync(Cb + (wm * 16) * 68 + wn * 32 + 16, acc[1], 68, wmma::mem_row_major);
    __syncthreads();
}

// ---------------- tile GEMM + fused LSTM cell ----------------
// h_out: rounded h (GEMM operand). h_extra_r: rounded copy (nullable).
// h_extra_f: FULL fp32 copy (nullable) for non-GEMM consumers.
__device__ __forceinline__ void gemm_lstm_tile(
    int tn, int tm,
    const float* __restrict__ A1, int lda1, int K1,
    const float* __restrict__ A2, int lda2, int K2,
    const float* __restrict__ W, int ldw,
    const float* __restrict__ bias,
    float* __restrict__ c_state,
    float* __restrict__ h_out,
    float* __restrict__ h_extra_r,
    float* __restrict__ h_extra_f, size_t extra_stride,
    float* __restrict__ smem)
{
    const int bn = tn * 64;
    const int bm = tm * 64;
    gemm_core_tf32(bn, bm, A1, lda1, K1, A2, lda2, K2, W, ldw, smem);
    const float* C0 = smem;
    const float* C1 = smem + 4608;

    const int tid = threadIdx.x;
#pragma unroll
    for (int t = 0; t < 2; t++) {
        int idx = tid + t * TPB;
        int r = idx >> 4;          // row in tile (batch)
        int jj = idx & 15;         // gate-quad within tile
        int b = bm + r;
        int ncol = bn + 4 * jj;
        int j = ncol >> 2;
        int o = r * 68 + 4 * jj;
        float gi = sigf(C0[o + 0] + C1[o + 0] + bias[ncol + 0]);
        float gf = sigf(C0[o + 1] + C1[o + 1] + bias[ncol + 1]);
        float gg = tanhg(C0[o + 2] + C1[o + 2] + bias[ncol + 2]);
        float go = sigf(C0[o + 3] + C1[o + 3] + bias[ncol + 3]);
        float c = gf * c_state[b * HH + j] + gi * gg;
        c_state[b * HH + j] = c;
        float hf = go * tanhg(c);           // full precision h
        float hr = to_tf32(hf);             // rounded (GEMM operand form)
        h_out[b * HH + j] = hr;
        if (h_extra_r) h_extra_r[(size_t)b * extra_stride + j] = hr;
        if (h_extra_f) h_extra_f[(size_t)b * extra_stride + j] = hf;
    }
    __syncthreads();
}

// ---------------- plain tile GEMM: C[m,n] = sum_k A[m,k]*W[n,k] (+bias) ------
__device__ __forceinline__ void gemm_bias_tile(
    int tn, int tm,
    const float* __restrict__ A, int lda,
    const float* __restrict__ W, int ldw,
    const float* __restrict__ bias,
    float* __restrict__ C, int N, int K,
    float* __restrict__ smem)
{
    const int bn = tn * 64;
    const int bm = tm * 64;
    gemm_core_tf32(bn, bm, A, lda, K, A, lda, 0, W, ldw, smem);
    const float* C0 = smem;
    const float* C1 = smem + 4608;

    const int tid = threadIdx.x;
#pragma unroll
    for (int t = 0; t < 2; t++) {
        int idx = tid + t * TPB;
        int r = idx >> 4;
        int c4 = idx & 15;
        int m = bm + r;
        int n = bn + 4 * c4;
        int o = r * 68 + 4 * c4;
        float4 v0 = *(const float4*)&C0[o];
        float4 v1 = *(const float4*)&C1[o];
        float4 v = make_float4(v0.x + v1.x, v0.y + v1.y, v0.z + v1.z, v0.w + v1.w);
        if (bias) {
            float4 bv = *(const float4*)&bias[n];
            v.x += bv.x; v.y += bv.y; v.z += bv.z; v.w += bv.w;
        }
        *(float4*)&C[(size_t)m * N + n] = v;
    }
    __syncthreads();
}

// ---------------- persistent mega-kernel ----------------
__global__ __launch_bounds__(TPB) void mega(
    const float* __restrict__ attn_b,
    const float* __restrict__ v_W,
    const float* __restrict__ fc_W,
    const float* __restrict__ fc_b,
    float* __restrict__ out)
{
    extern __shared__ __align__(16) float dyn[];   // 4 x 4608 floats (73.7 KB)
    __shared__ float sm[1024];

    const int bid = blockIdx.x;
    const int tid = threadIdx.x;
    const int tn = bid & 31;   // 32 n-tiles (N=2048)
    const int tm = bid >> 5;   // 4 m-tiles  (M=256)

    // ---------------- encoder: 512 steps, ONE grid barrier per step ----------------
    for (int t = 0; t < SS; t++) {
        int p = t & 1;
        gemm_lstm_tile(tn, tm, g_srcr + t * DD, SS * DD, DD,
                       g_h0[p], HH, HH, g_W0, 544, g_b0,
                       g_c0, g_h0[p ^ 1], nullptr, nullptr, 0, dyn);
        grid_barrier();  // h0(t) complete; L1(t) and L0(t+1) are conflict-free after
        gemm_lstm_tile(tn, tm, g_h0[p ^ 1], HH, HH,
                       g_h1[p], HH, HH, g_W1, 1024, g_b1,
                       g_c1, g_h1[p ^ 1],
                       g_enc_outs_r + (size_t)t * HH,
                       g_enc_outs + (size_t)t * HH, (size_t)SS * HH, dyn);
    }
    grid_barrier();  // enc_outs + final states complete

    // ---------------- enc_proj = enc_outs_r @ W_enc^T + attn_b ----------------
    for (int tt = bid; tt < 16384; tt += NB) {
        gemm_bias_tile(tt & 7, tt >> 3, g_enc_outs_r, HH, g_attnW, 2 * HH,
                       attn_b, g_enc_proj, HH, HH, dyn);
    }
    grid_barrier();

    // ---------------- decoder: 24 steps ----------------
    for (int it = 0; it < PLEN; it++) {
        int p = it & 1;

        // A: dp = h1 @ W_dec^T   (8 x 4 = 32 tiles)
        if (bid < 32) {
            gemm_bias_tile(bid & 7, bid >> 3, g_h1[p], HH, g_attnW + HH, 2 * HH,
                           nullptr, g_dp, HH, HH, dyn);
        }
        grid_barrier();

        // B: scores[b,s] = sum_h v[h]*tanh(ep[b,s,h]+dp[b,h]) — 2 b per block
        {
            int warp = tid >> 5, lane = tid & 31;
#pragma unroll 1
            for (int bb = 0; bb < 2; bb++) {
                int b = bid * 2 + bb;
                for (int i = tid; i < HH; i += TPB) {
                    sm[i] = g_dp[b * HH + i];
                    sm[512 + i] = v_W[i];
                }
                __syncthreads();
                const float* ep = g_enc_proj + (size_t)b * SS * HH;
                for (int s = warp; s < SS; s += 16) {
                    const float* row = ep + (size_t)s * HH;
                    float acc = 0.f;
#pragma unroll
                    for (int h0 = 0; h0 < 4; h0++) {
                        int h = h0 * 128 + lane * 4;
                        float4 r = *(const float4*)&row[h];
                        float4 d = *(const float4*)&sm[h];
                        float4 v = *(const float4*)&sm[512 + h];
                        acc += v.x * fast_tanh(r.x + d.x)
                             + v.y * fast_tanh(r.y + d.y)
                             + v.z * fast_tanh(r.z + d.z)
                             + v.w * fast_tanh(r.w + d.w);
                    }
#pragma unroll
                    for (int off = 16; off > 0; off >>= 1)
                        acc += __shfl_down_sync(0xffffffffu, acc, off);
                    if (lane == 0) g_sc[b * SS + s] = acc;
                }
                __syncthreads();
            }
        }
        grid_barrier();

        // C: softmax over s — 2 b per block
        {
#pragma unroll 1
            for (int bb = 0; bb < 2; bb++) {
                int b = bid * 2 + bb;
                float m = -1e30f;
                for (int s = tid; s < SS; s += TPB) m = fmaxf(m, g_sc[b * SS + s]);
                sm[tid] = m; __syncthreads();
                for (int off = TPB / 2; off > 0; off >>= 1) {
                    if (tid < off) sm[tid] = fmaxf(sm[tid], sm[tid + off]);
                    __syncthreads();
                }
                m = sm[0]; __syncthreads();
                float sum = 0.f;
                for (int s = tid; s < SS; s += TPB) {
                    float e = __expf(g_sc[b * SS + s] - m);
                    g_wsm[b * SS + s] = e;
                    sum += e;
                }
                sm[tid] = sum; __syncthreads();
                for (int off = TPB / 2; off > 0; off >>= 1) {
                    if (tid < off) sm[tid] += sm[tid + off];
                    __syncthreads();
                }
                float inv = 1.f / sm[0]; __syncthreads();
                for (int s = tid; s < SS; s += TPB) g_wsm[b * SS + s] *= inv;
            }
        }
        grid_barrier();

        // D: context (from FULL fp32 enc_outs) -> xcat rounded; xcat[:,0] = dec_in
        {
#pragma unroll 1
            for (int bb = 0; bb < 2; bb++) {
                int b = bid * 2 + bb;
                for (int i = tid; i < SS; i += TPB) sm[i] = g_wsm[b * SS + i];
                __syncthreads();
                const float* base = g_enc_outs + (size_t)b * SS * HH;
                float a0 = 0.f;
#pragma unroll 4
                for (int s = 0; s < SS; s++) {
                    a0 += sm[s] * base[(size_t)s * HH + tid];
                }
                g_xcat[b * XS + 1 + tid] = to_tf32(a0);
                if (tid == 0) g_xcat[b * XS] = to_tf32(g_decin[b]);
                __syncthreads();
            }
        }
        grid_barrier();

        // E: decoder LSTM layer 0 (K = 544 + 512, chunk-aligned)
        gemm_lstm_tile(tn, tm, g_xcat, XS, XS,
                       g_h0[p], HH, HH, g_Wd0, WD0K, g_bd0,
                       g_c0, g_h0[p ^ 1], nullptr, nullptr, 0, dyn);
        grid_barrier();

        // F: decoder LSTM layer 1 (K = 1024); full h copy for stage G
        gemm_lstm_tile(tn, tm, g_h0[p ^ 1], HH, HH,
                       g_h1[p], HH, HH, g_Wd1, 1024, g_bd1,
                       g_c1, g_h1[p ^ 1], nullptr, g_h1f, HH, dyn);
        grid_barrier();

        // G: pred = h1f (FULL fp32) . fc_W  (16 blocks x 16 warps = 256 b)
        if (bid < 16) {
            int warp = tid >> 5, lane = tid & 31;
            int b = bid * 16 + warp;
            const float* h1r = g_h1f + b * HH;
            float acc = 0.f;
            for (int h = lane; h < HH; h += 32) acc += h1r[h] * fc_W[h];
#pragma unroll
            for (int off = 16; off > 0; off >>= 1)
                acc += __shfl_down_sync(0xffffffffu, acc, off);
            if (lane == 0) {
                float pred = acc + fc_b[0];
                out[b * PLEN + it] = pred;
                g_decin[b] = 0.8f * pred + 0.2f * g_hist[b];
            }
        }
        // G(t)'s decin write is ordered before D(t+1)'s read by the barriers
        // after A(t+1); dp overwrite in A(t+1) is ordered after B(t).
    }
}

// ---------------- launch ----------------
extern "C" void kernel_launch(void* const* d_in, const int* in_sizes, int n_in,
                              void* d_out, int out_size) {
    (void)in_sizes; (void)n_in; (void)out_size;
    const float* src    = (const float*)d_in[0];
    const float* ew0    = (const float*)d_in[1];
    const float* eu0    = (const float*)d_in[2];
    const float* ebi0   = (const float*)d_in[3];
    const float* ebh0   = (const float*)d_in[4];
    const float* ew1    = (const float*)d_in[5];
    const float* eu1    = (const float*)d_in[6];
    const float* ebi1   = (const float*)d_in[7];
    const float* ebh1   = (const float*)d_in[8];
    const float* dw0    = (const float*)d_in[9];
    const float* du0    = (const float*)d_in[10];
    const float* dbi0   = (const float*)d_in[11];
    const float* dbh0   = (const float*)d_in[12];
    const float* dw1    = (const float*)d_in[13];
    const float* du1    = (const float*)d_in[14];
    const float* dbi1   = (const float*)d_in[15];
    const float* dbh1   = (const float*)d_in[16];
    const float* attn_W = (const float*)d_in[17];
    const float* attn_b = (const float*)d_in[18];
    const float* v_W    = (const float*)d_in[19];
    const float* fc_W   = (const float*)d_in[20];
    const float* fc_b   = (const float*)d_in[21];
    float* out = (float*)d_out;

    static int smem_set = 0;
    const int dyn_bytes = 4 * 4608 * 4;   // 73728
    if (!smem_set) {
        cudaFuncSetAttribute(mega, cudaFuncAttributeMaxDynamicSharedMemorySize,
                             dyn_bytes);
        smem_set = 1;
    }

    prep_all<<<2048, 256>>>(src, ew0, eu0, ebi0, ebh0, ew1, eu1, ebi1, ebh1,
                            dw0, du0, dbi0, dbh0, dw1, du1, dbi1, dbh1, attn_W);
    mega<<<NB, TPB, dyn_bytes>>>(attn_b, v_W, fc_W, fc_b, out);
}